// round 10
// baseline (speedup 1.0000x reference)
#include <cuda_runtime.h>
#include <cuda_bf16.h>
#include <cuda_fp16.h>
#include <cstdint>
#include <math.h>

#define Bv 64
#define Tv 512
#define Iv 1024
#define Hv 1024
#define Gv 4096   // 4*H

// ---------------------------------------------------------------------------
// Static device scratch
// ---------------------------------------------------------------------------
__device__ float g_Gx[(size_t)Tv * Bv * Gv];              // 512MB [T][B][4H]
__device__ __nv_bfloat16 g_x_hi[(size_t)Bv * Tv * Iv];    // 64MB
__device__ __nv_bfloat16 g_x_lo[(size_t)Bv * Tv * Iv];    // 64MB
__device__ __nv_bfloat16 g_Wih_hi[(size_t)Gv * Iv];       // 8MB
__device__ __nv_bfloat16 g_Wih_lo[(size_t)Gv * Iv];
__device__ __half g_Whh_f16[(size_t)Gv * Hv];             // 8MB, single fp16
__device__ __half g_h[2][Bv * Hv];                        // fp16 h (single)
__device__ float g_c[Bv * Hv];
__device__ unsigned int g_bar;

// ---------------------------------------------------------------------------
// Helpers
// ---------------------------------------------------------------------------
__device__ __forceinline__ uint32_t smem_u32(const void* p) {
    uint32_t a;
    asm("{ .reg .u64 t; cvta.to.shared.u64 t, %1; cvt.u32.u64 %0, t; }"
        : "=r"(a) : "l"(p));
    return a;
}

#define SWZ128(o) ((o) ^ (((o) >> 3) & 0x70))

__device__ __forceinline__ void cp16(uint32_t dst, const void* src) {
    asm volatile("cp.async.cg.shared.global [%0], [%1], 16;" :: "r"(dst), "l"(src));
}
#define CP_COMMIT() asm volatile("cp.async.commit_group;" ::: "memory")
#define CP_WAIT(n)  asm volatile("cp.async.wait_group %0;" :: "n"(n) : "memory")

__device__ __forceinline__ void ldsm4(uint32_t* r, uint32_t addr) {
    asm volatile("ldmatrix.sync.aligned.m8n8.x4.shared.b16 {%0,%1,%2,%3}, [%4];"
        : "=r"(r[0]), "=r"(r[1]), "=r"(r[2]), "=r"(r[3]) : "r"(addr));
}

__device__ __forceinline__ void mma16816(float* d, const uint32_t* a,
                                         uint32_t b0, uint32_t b1) {
    asm volatile(
        "mma.sync.aligned.m16n8k16.row.col.f32.bf16.bf16.f32 "
        "{%0,%1,%2,%3}, {%4,%5,%6,%7}, {%8,%9}, {%0,%1,%2,%3};"
        : "+f"(d[0]), "+f"(d[1]), "+f"(d[2]), "+f"(d[3])
        : "r"(a[0]), "r"(a[1]), "r"(a[2]), "r"(a[3]), "r"(b0), "r"(b1));
}

__device__ __forceinline__ void mma16816h(float* d, const uint32_t* a,
                                          uint32_t b0, uint32_t b1) {
    asm volatile(
        "mma.sync.aligned.m16n8k16.row.col.f32.f16.f16.f32 "
        "{%0,%1,%2,%3}, {%4,%5,%6,%7}, {%8,%9}, {%0,%1,%2,%3};"
        : "+f"(d[0]), "+f"(d[1]), "+f"(d[2]), "+f"(d[3])
        : "r"(a[0]), "r"(a[1]), "r"(a[2]), "r"(a[3]), "r"(b0), "r"(b1));
}

__device__ __forceinline__ float sigm(float x) {
    return 1.0f / (1.0f + __expf(-x));
}
__device__ __forceinline__ float tanh_fast(float x) {
    float cx = fminf(fmaxf(x, -10.0f), 10.0f);
    float e = __expf(2.0f * cx);
    return (e - 1.0f) / (e + 1.0f);
}

// ---------------------------------------------------------------------------
// bf16 3-pass warp MMA over one K-chunk of 64 (input GEMM, proven R4-R9).
// ---------------------------------------------------------------------------
template <int NT>
__device__ __forceinline__ void warp_mma_chunk(
    uint32_t aHi, uint32_t aLo, uint32_t bHi, uint32_t bLo,
    int mrow, int nbase, int lane, float acc[][4])
{
    const int arowoff = (lane & 7) + ((lane >> 3) & 1) * 8;
    const int nrowoff = (lane & 7) + ((lane >> 4) & 1) * 8;
    #pragma unroll
    for (int kk = 0; kk < 4; kk++) {
        uint32_t ah[2][4], al[2][4], bh[NT][4], bl[NT][4];
        const int akoff = kk * 32 + (lane >> 4) * 16;
        const int bkoff = kk * 32 + ((lane >> 3) & 1) * 16;
        #pragma unroll
        for (int m = 0; m < 2; m++) {
            uint32_t off = SWZ128((uint32_t)((mrow + m * 16 + arowoff) * 128 + akoff));
            ldsm4(ah[m], aHi + off);
            ldsm4(al[m], aLo + off);
        }
        #pragma unroll
        for (int jb = 0; jb < NT; jb++) {
            uint32_t off = SWZ128((uint32_t)((nbase + jb * 16 + nrowoff) * 128 + bkoff));
            ldsm4(bh[jb], bHi + off);
            ldsm4(bl[jb], bLo + off);
        }
        #pragma unroll
        for (int jb = 0; jb < NT; jb++)
            #pragma unroll
            for (int m = 0; m < 2; m++) {
                mma16816(acc[m * 2 * NT + jb * 2],     ah[m], bh[jb][0], bh[jb][1]);
                mma16816(acc[m * 2 * NT + jb * 2 + 1], ah[m], bh[jb][2], bh[jb][3]);
            }
        #pragma unroll
        for (int jb = 0; jb < NT; jb++)
            #pragma unroll
            for (int m = 0; m < 2; m++) {
                mma16816(acc[m * 2 * NT + jb * 2],     al[m], bh[jb][0], bh[jb][1]);
                mma16816(acc[m * 2 * NT + jb * 2 + 1], al[m], bh[jb][2], bh[jb][3]);
            }
        #pragma unroll
        for (int jb = 0; jb < NT; jb++)
            #pragma unroll
            for (int m = 0; m < 2; m++) {
                mma16816(acc[m * 2 * NT + jb * 2],     ah[m], bl[jb][0], bl[jb][1]);
                mma16816(acc[m * 2 * NT + jb * 2 + 1], ah[m], bl[jb][2], bl[jb][3]);
            }
    }
}

// ---------------------------------------------------------------------------
// fp16 SINGLE-pass warp MMA over one 64-wide K sub-tile (recurrence).
// ---------------------------------------------------------------------------
__device__ __forceinline__ void warp_mma_1p(
    uint32_t aT, uint32_t bW, int mrow, int nbase, int lane, float acc[][4])
{
    const int arowoff = (lane & 7) + ((lane >> 3) & 1) * 8;
    const int nrowoff = (lane & 7) + ((lane >> 4) & 1) * 8;
    #pragma unroll
    for (int kk = 0; kk < 4; kk++) {
        uint32_t ah[2][4], bw[4];
        const int akoff = kk * 32 + (lane >> 4) * 16;
        const int bkoff = kk * 32 + ((lane >> 3) & 1) * 16;
        #pragma unroll
        for (int m = 0; m < 2; m++) {
            uint32_t off = SWZ128((uint32_t)((mrow + m * 16 + arowoff) * 128 + akoff));
            ldsm4(ah[m], aT + off);
        }
        {
            uint32_t off = SWZ128((uint32_t)((nbase + nrowoff) * 128 + bkoff));
            ldsm4(bw, bW + off);
        }
        #pragma unroll
        for (int m = 0; m < 2; m++) {
            mma16816h(acc[m * 2],     ah[m], bw[0], bw[1]);
            mma16816h(acc[m * 2 + 1], ah[m], bw[2], bw[3]);
        }
    }
}

// ---------------------------------------------------------------------------
// Prep kernels (device symbols bound in device code — R3 lesson).
// ---------------------------------------------------------------------------
__global__ void split_kernel(const float* __restrict__ src, int which, size_t n) {
    size_t stride = (size_t)gridDim.x * blockDim.x;
    if (which == 2) {   // Whh -> single fp16
        for (size_t i = (size_t)blockIdx.x * blockDim.x + threadIdx.x; i < n; i += stride)
            g_Whh_f16[i] = __float2half(src[i]);
        return;
    }
    __nv_bfloat16* hi = (which == 0) ? g_x_hi : g_Wih_hi;
    __nv_bfloat16* lo = (which == 0) ? g_x_lo : g_Wih_lo;
    for (size_t i = (size_t)blockIdx.x * blockDim.x + threadIdx.x; i < n; i += stride) {
        float v = src[i];
        __nv_bfloat16 h = __float2bfloat16(v);
        hi[i] = h;
        lo[i] = __float2bfloat16(v - __bfloat162float(h));
    }
}

__global__ void init_state_kernel() {
    int i = blockIdx.x * blockDim.x + threadIdx.x;
    if (i == 0) g_bar = 0u;
    if (i < Bv * Hv) {
        g_h[0][i] = __float2half(0.0f);
        g_c[i] = 0.0f;
    }
}

// ---------------------------------------------------------------------------
// Input GEMM (bf16 HMMA 3-pass, unchanged from R4-R9 pass)
// ---------------------------------------------------------------------------
#define G_STAGE 65536
#define G_SMEM  (2 * G_STAGE)

__device__ __forceinline__ void gemm_load(uint32_t sb, int s, int k0,
                                          int m0, int n0, int tid) {
    uint32_t base = sb + (uint32_t)s * G_STAGE;
    #pragma unroll
    for (int r = 0; r < 8; r++) {
        int idx = tid + r * 256;
        int hf = idx >> 10, rem = idx & 1023;
        int row = rem >> 3, c = rem & 7;
        const __nv_bfloat16* src = (hf ? g_x_lo : g_x_hi)
                                   + (size_t)(m0 + row) * Iv + k0 + c * 8;
        cp16(base + hf * 16384 + SWZ128((uint32_t)(row * 128 + c * 16)), src);
    }
    #pragma unroll
    for (int r = 0; r < 8; r++) {
        int idx = tid + r * 256;
        int hf = idx >> 10, rem = idx & 1023;
        int row = rem >> 3, c = rem & 7;
        const __nv_bfloat16* src = (hf ? g_Wih_lo : g_Wih_hi)
                                   + (size_t)(n0 + row) * Iv + k0 + c * 8;
        cp16(base + 32768 + hf * 16384 + SWZ128((uint32_t)(row * 128 + c * 16)), src);
    }
}

__global__ void __launch_bounds__(256, 1) gemm_in_mma(const float* __restrict__ bias)
{
    extern __shared__ char smem[];
    uint32_t sb = smem_u32(smem);
    const int tid = threadIdx.x, lane = tid & 31, wid = tid >> 5;
    const int m0 = blockIdx.y * 128, n0 = blockIdx.x * 128;

    float acc[16][4];
    #pragma unroll
    for (int i = 0; i < 16; i++)
        #pragma unroll
        for (int j = 0; j < 4; j++) acc[i][j] = 0.0f;

    gemm_load(sb, 0, 0, m0, n0, tid);
    CP_COMMIT();

    const int mrow = (wid & 3) * 32, nbase = (wid >> 2) * 64;
    for (int it = 0; it < 16; it++) {
        const int s = it & 1;
        if (it + 1 < 16) {
            gemm_load(sb, (it + 1) & 1, (it + 1) * 64, m0, n0, tid);
            CP_COMMIT();
            CP_WAIT(1);
        } else {
            CP_WAIT(0);
        }
        __syncthreads();
        uint32_t base = sb + (uint32_t)s * G_STAGE;
        warp_mma_chunk<4>(base, base + 16384, base + 32768, base + 49152,
                          mrow, nbase, lane, acc);
        __syncthreads();
    }

    #pragma unroll
    for (int m = 0; m < 2; m++)
        #pragma unroll
        for (int j = 0; j < 8; j++) {
            float* a = acc[m * 8 + j];
            int gr = m0 + (wid & 3) * 32 + m * 16 + (lane >> 2);
            int n  = n0 + (wid >> 2) * 64 + j * 8 + 2 * (lane & 3);
            float b0 = bias[n], b1 = bias[n + 1];
            int bi0 = gr >> 9, tt0 = gr & 511;
            float* o0 = g_Gx + ((size_t)tt0 * Bv + bi0) * Gv + n;
            o0[0] = a[0] + b0; o0[1] = a[1] + b1;
            int gr2 = gr + 8, bi2 = gr2 >> 9, tt2 = gr2 & 511;
            float* o2 = g_Gx + ((size_t)tt2 * Bv + bi2) * Gv + n;
            o2[0] = a[2] + b0; o2[1] = a[3] + b1;
        }
}

// ---------------------------------------------------------------------------
// Persistent LSTM recurrence (fp16 single-pass, full-step prefetch).
// 128 CTAs x 256 threads, 1 CTA/SM. CTA owns 8 hidden cols (32 gate rows).
// W_f16 (64KB) SMEM-resident. Per step: ALL 8 K-chunks (128 wide each) of the
// h tile issued as 8 cp.async groups up front + Gx as a 9th group; chunks
// consumed with monotone wait_group — no per-chunk L2 latency exposure.
// Single global barrier per step.
// ---------------------------------------------------------------------------
#define WS    0                            /* 16 sub-chunks x 4KB = 64KB */
#define AB    65536                        /* 8 chunk buffers x 16KB = 128KB */
#define GXS   (AB + 8 * 16384)             /* 196608: 64 x 144B = 9216 */
#define GS0   (GXS + 9216)                 /* 205824: 64 x 33 fp32 = 8448 */
#define GS1   (GS0 + 8448)                 /* 214272 */
#define P_SMEM (GS1 + 8448)                /* 222720 (~217.5KB) */

// Load A tile for K-chunk of 128 (two 64-wide sub-tiles, 16KB total).
__device__ __forceinline__ void persist_loadA(uint32_t sb, int st, int k0,
                                              const __half* __restrict__ hIn,
                                              int tid) {
    uint32_t base = sb + AB + (uint32_t)st * 16384;
    #pragma unroll
    for (int r = 0; r < 4; r++) {          // 1024 cp16 = 16KB
        int idx = tid + r * 256;
        int sub = idx >> 9, rem = idx & 511;
        int row = rem >> 3, c = rem & 7;   // row = batch 0..63
        const __half* src = hIn + (size_t)row * Hv + k0 + sub * 64 + c * 8;
        cp16(base + sub * 8192 + SWZ128((uint32_t)(row * 128 + c * 16)), src);
    }
}

__global__ void __launch_bounds__(256, 1) lstm_persistent(float* __restrict__ dout)
{
    extern __shared__ char smem[];
    uint32_t sb = smem_u32(smem);
    const int tid = threadIdx.x, lane = tid & 31, wid = tid >> 5;
    const int j0 = blockIdx.x * 8;
    const int par = wid >> 2;                  // chunk parity this warp computes
    const int mrow = (wid & 1) * 32;
    const int nbase = ((wid >> 1) & 1) * 16;

    // ---- Preload W_f16 tile: 32 gate rows x K=1024 = 64KB, sub-chunk-major
    #pragma unroll
    for (int r = 0; r < 16; r++) {             // 4096 cp16
        int idx = tid + r * 256;
        int chunk = idx >> 8, within = idx & 255;
        int row = within >> 3, c = within & 7;
        int gate = row >> 3, jc = row & 7;
        const __half* src = g_Whh_f16
            + (size_t)(gate * Hv + j0 + jc) * Hv + chunk * 64 + c * 8;
        cp16(sb + WS + chunk * 4096 + SWZ128((uint32_t)(row * 128 + c * 16)), src);
    }
    CP_COMMIT();
    CP_WAIT(0);
    __syncthreads();

    float* Gs0 = (float*)(smem + GS0);
    float* Gs1 = (float*)(smem + GS1);
    float* gxs = (float*)(smem + GXS);

    for (int t = 0; t < Tv; t++) {
        const __half* hIn = g_h[t & 1];
        __half* hOut      = g_h[(t + 1) & 1];

        float acc[4][4];
        #pragma unroll
        for (int i = 0; i < 4; i++)
            #pragma unroll
            for (int j = 0; j < 4; j++) acc[i][j] = 0.0f;

        // ---- Issue ALL 8 h chunk loads (groups 0-7), then Gx (group 8)
        #pragma unroll
        for (int c = 0; c < 8; c++) {
            persist_loadA(sb, c, c * 128, hIn, tid);
            CP_COMMIT();
        }
        {
            const float* gxbase = g_Gx + ((size_t)t * Bv) * Gv + j0;
            #pragma unroll
            for (int r = 0; r < 2; r++) {       // 512 cp16 = 8KB
                int idx = tid + r * 256;
                int b = idx >> 3;
                int gate = (idx >> 1) & 3, hf = idx & 1;
                cp16(sb + GXS + (uint32_t)(b * 144 + gate * 32 + hf * 16),
                     gxbase + (size_t)b * Gv + gate * Hv + hf * 4);
            }
            CP_COMMIT();
        }

        // ---- Consume chunks as they arrive (monotone wait_group)
        #pragma unroll
        for (int it = 0; it < 8; it++) {
            if      (it == 0) CP_WAIT(8);
            else if (it == 1) CP_WAIT(7);
            else if (it == 2) CP_WAIT(6);
            else if (it == 3) CP_WAIT(5);
            else if (it == 4) CP_WAIT(4);
            else if (it == 5) CP_WAIT(3);
            else if (it == 6) CP_WAIT(2);
            else              CP_WAIT(1);
            __syncthreads();
            if ((it & 1) == par) {
                uint32_t aT = sb + AB + (uint32_t)it * 16384;
                warp_mma_1p(aT,        sb + WS + (uint32_t)(2 * it) * 4096,
                            mrow, nbase, lane, acc);
                warp_mma_1p(aT + 8192, sb + WS + (uint32_t)(2 * it + 1) * 4096,
                            mrow, nbase, lane, acc);
            }
        }
        CP_WAIT(0);   // Gx group

        // Stage partial gates (per k-parity buffer)
        float* Gs = par ? Gs1 : Gs0;
        #pragma unroll
        for (int m = 0; m < 2; m++)
            #pragma unroll
            for (int p = 0; p < 2; p++) {
                float* a = acc[m * 2 + p];
                int r0 = mrow + m * 16 + (lane >> 2);
                int cc = nbase + p * 8 + 2 * (lane & 3);
                Gs[r0 * 33 + cc]           = a[0];
                Gs[r0 * 33 + cc + 1]       = a[1];
                Gs[(r0 + 8) * 33 + cc]     = a[2];
                Gs[(r0 + 8) * 33 + cc + 1] = a[3];
            }
        __syncthreads();

        // Fused cell update: 512 cells (64 batch x 8 hidden cols)
        #pragma unroll
        for (int p = 0; p < 2; p++) {
            int cell = tid + p * 256;
            int b = cell >> 3, jc = cell & 7;
            const float* gx = gxs + b * 36;
            float gi = Gs0[b * 33 + jc]      + Gs1[b * 33 + jc]      + gx[jc];
            float gf = Gs0[b * 33 + 8 + jc]  + Gs1[b * 33 + 8 + jc]  + gx[8 + jc];
            float gg = Gs0[b * 33 + 16 + jc] + Gs1[b * 33 + 16 + jc] + gx[16 + jc];
            float go = Gs0[b * 33 + 24 + jc] + Gs1[b * 33 + 24 + jc] + gx[24 + jc];

            int hidx = b * Hv + j0 + jc;
            float c_old = g_c[hidx];
            float cn = sigm(gf) * c_old + sigm(gi) * tanh_fast(gg);
            float hn = sigm(go) * tanh_fast(cn);
            g_c[hidx] = cn;

            hOut[hidx] = __float2half(hn);

            dout[(size_t)b * Tv * Hv + (size_t)t * Hv + j0 + jc] = hn;
            if (t == Tv - 1) {
                size_t obase = (size_t)Bv * Tv * Hv;
                dout[obase + hidx] = hn;                    // h_T
                dout[obase + (size_t)Bv * Hv + hidx] = cn;  // c_T
            }
        }

        // ---- Global barrier (release-arrive by tid0, acquire-spin, fanout)
        __syncthreads();
        if (tid == 0) {
            unsigned int ignored;
            asm volatile("atom.add.release.gpu.u32 %0, [%1], 1;"
                         : "=r"(ignored) : "l"(&g_bar) : "memory");
            unsigned int target = 128u * (unsigned int)(t + 1);
            unsigned int cur;
            do {
                asm volatile("ld.acquire.gpu.u32 %0, [%1];"
                             : "=r"(cur) : "l"(&g_bar) : "memory");
                if (cur >= target) break;
                asm volatile("nanosleep.u32 16;");
            } while (true);
        }
        __syncthreads();
    }
}

// ---------------------------------------------------------------------------
// Launch
// ---------------------------------------------------------------------------
extern "C" void kernel_launch(void* const* d_in, const int* in_sizes, int n_in,
                              void* d_out, int out_size)
{
    const float* x    = (const float*)d_in[0];  // [B, T, I]
    const float* Wih  = (const float*)d_in[1];  // [4H, I]
    const float* Whh  = (const float*)d_in[2];  // [4H, H]
    const float* bias = (const float*)d_in[3];  // [4H]
    float* out = (float*)d_out;
    (void)in_sizes; (void)n_in; (void)out_size;

    cudaFuncSetAttribute(gemm_in_mma,     cudaFuncAttributeMaxDynamicSharedMemorySize, G_SMEM);
    cudaFuncSetAttribute(lstm_persistent, cudaFuncAttributeMaxDynamicSharedMemorySize, P_SMEM);

    split_kernel<<<8192, 256>>>(x,   0, (size_t)Bv * Tv * Iv);
    split_kernel<<<4096, 256>>>(Wih, 1, (size_t)Gv * Iv);
    split_kernel<<<4096, 256>>>(Whh, 2, (size_t)Gv * Hv);
    init_state_kernel<<<(Bv * Hv + 255) / 256, 256>>>();

    dim3 ggrid(Gv / 128, (Bv * Tv) / 128);   // (32, 256)
    gemm_in_mma<<<ggrid, 256, G_SMEM>>>(bias);

    lstm_persistent<<<128, 256, P_SMEM>>>(out);
}

// round 11
// speedup vs baseline: 1.4418x; 1.4418x over previous
#include <cuda_runtime.h>
#include <cuda_bf16.h>
#include <cuda_fp16.h>
#include <cstdint>
#include <math.h>

#define Bv 64
#define Tv 512
#define Iv 1024
#define Hv 1024
#define Gv 4096   // 4*H

// ---------------------------------------------------------------------------
// Static device scratch
// ---------------------------------------------------------------------------
__device__ float g_Gx[(size_t)Tv * Bv * Gv];              // 512MB [T][B][4H]
__device__ __nv_bfloat16 g_x_hi[(size_t)Bv * Tv * Iv];    // 64MB
__device__ __nv_bfloat16 g_x_lo[(size_t)Bv * Tv * Iv];    // 64MB
__device__ __nv_bfloat16 g_Wih_hi[(size_t)Gv * Iv];       // 8MB
__device__ __nv_bfloat16 g_Wih_lo[(size_t)Gv * Iv];
__device__ __half g_Whh_f16[(size_t)Gv * Hv];             // 8MB, single fp16
__device__ __half g_h[2][Bv * Hv];                        // fp16 h (single)
__device__ unsigned int g_bar;

// ---------------------------------------------------------------------------
// Helpers
// ---------------------------------------------------------------------------
__device__ __forceinline__ uint32_t smem_u32(const void* p) {
    uint32_t a;
    asm("{ .reg .u64 t; cvta.to.shared.u64 t, %1; cvt.u32.u64 %0, t; }"
        : "=r"(a) : "l"(p));
    return a;
}

#define SWZ128(o) ((o) ^ (((o) >> 3) & 0x70))

__device__ __forceinline__ void cp16(uint32_t dst, const void* src) {
    asm volatile("cp.async.cg.shared.global [%0], [%1], 16;" :: "r"(dst), "l"(src));
}
#define CP_COMMIT() asm volatile("cp.async.commit_group;" ::: "memory")
#define CP_WAIT(n)  asm volatile("cp.async.wait_group %0;" :: "n"(n) : "memory")

__device__ __forceinline__ void ldsm4(uint32_t* r, uint32_t addr) {
    asm volatile("ldmatrix.sync.aligned.m8n8.x4.shared.b16 {%0,%1,%2,%3}, [%4];"
        : "=r"(r[0]), "=r"(r[1]), "=r"(r[2]), "=r"(r[3]) : "r"(addr));
}

__device__ __forceinline__ void mma16816(float* d, const uint32_t* a,
                                         uint32_t b0, uint32_t b1) {
    asm volatile(
        "mma.sync.aligned.m16n8k16.row.col.f32.bf16.bf16.f32 "
        "{%0,%1,%2,%3}, {%4,%5,%6,%7}, {%8,%9}, {%0,%1,%2,%3};"
        : "+f"(d[0]), "+f"(d[1]), "+f"(d[2]), "+f"(d[3])
        : "r"(a[0]), "r"(a[1]), "r"(a[2]), "r"(a[3]), "r"(b0), "r"(b1));
}

__device__ __forceinline__ void mma16816h(float* d, const uint32_t* a,
                                          uint32_t b0, uint32_t b1) {
    asm volatile(
        "mma.sync.aligned.m16n8k16.row.col.f32.f16.f16.f32 "
        "{%0,%1,%2,%3}, {%4,%5,%6,%7}, {%8,%9}, {%0,%1,%2,%3};"
        : "+f"(d[0]), "+f"(d[1]), "+f"(d[2]), "+f"(d[3])
        : "r"(a[0]), "r"(a[1]), "r"(a[2]), "r"(a[3]), "r"(b0), "r"(b1));
}

__device__ __forceinline__ float sigm(float x) {
    return 1.0f / (1.0f + __expf(-x));
}
__device__ __forceinline__ float tanh_fast(float x) {
    float cx = fminf(fmaxf(x, -10.0f), 10.0f);
    float e = __expf(2.0f * cx);
    return (e - 1.0f) / (e + 1.0f);
}

// ---------------------------------------------------------------------------
// bf16 3-pass warp MMA over one K-chunk of 64 (input GEMM, proven R4-R9).
// ---------------------------------------------------------------------------
template <int NT>
__device__ __forceinline__ void warp_mma_chunk(
    uint32_t aHi, uint32_t aLo, uint32_t bHi, uint32_t bLo,
    int mrow, int nbase, int lane, float acc[][4])
{
    const int arowoff = (lane & 7) + ((lane >> 3) & 1) * 8;
    const int nrowoff = (lane & 7) + ((lane >> 4) & 1) * 8;
    #pragma unroll
    for (int kk = 0; kk < 4; kk++) {
        uint32_t ah[2][4], al[2][4], bh[NT][4], bl[NT][4];
        const int akoff = kk * 32 + (lane >> 4) * 16;
        const int bkoff = kk * 32 + ((lane >> 3) & 1) * 16;
        #pragma unroll
        for (int m = 0; m < 2; m++) {
            uint32_t off = SWZ128((uint32_t)((mrow + m * 16 + arowoff) * 128 + akoff));
            ldsm4(ah[m], aHi + off);
            ldsm4(al[m], aLo + off);
        }
        #pragma unroll
        for (int jb = 0; jb < NT; jb++) {
            uint32_t off = SWZ128((uint32_t)((nbase + jb * 16 + nrowoff) * 128 + bkoff));
            ldsm4(bh[jb], bHi + off);
            ldsm4(bl[jb], bLo + off);
        }
        #pragma unroll
        for (int jb = 0; jb < NT; jb++)
            #pragma unroll
            for (int m = 0; m < 2; m++) {
                mma16816(acc[m * 2 * NT + jb * 2],     ah[m], bh[jb][0], bh[jb][1]);
                mma16816(acc[m * 2 * NT + jb * 2 + 1], ah[m], bh[jb][2], bh[jb][3]);
            }
        #pragma unroll
        for (int jb = 0; jb < NT; jb++)
            #pragma unroll
            for (int m = 0; m < 2; m++) {
                mma16816(acc[m * 2 * NT + jb * 2],     al[m], bh[jb][0], bh[jb][1]);
                mma16816(acc[m * 2 * NT + jb * 2 + 1], al[m], bh[jb][2], bh[jb][3]);
            }
        #pragma unroll
        for (int jb = 0; jb < NT; jb++)
            #pragma unroll
            for (int m = 0; m < 2; m++) {
                mma16816(acc[m * 2 * NT + jb * 2],     ah[m], bl[jb][0], bl[jb][1]);
                mma16816(acc[m * 2 * NT + jb * 2 + 1], ah[m], bl[jb][2], bl[jb][3]);
            }
    }
}

// ---------------------------------------------------------------------------
// fp16 SINGLE-pass warp MMA over one 64-wide K sub-tile (recurrence).
// ---------------------------------------------------------------------------
__device__ __forceinline__ void warp_mma_1p(
    uint32_t aT, uint32_t bW, int mrow, int nbase, int lane, float acc[][4])
{
    const int arowoff = (lane & 7) + ((lane >> 3) & 1) * 8;
    const int nrowoff = (lane & 7) + ((lane >> 4) & 1) * 8;
    #pragma unroll
    for (int kk = 0; kk < 4; kk++) {
        uint32_t ah[2][4], bw[4];
        const int akoff = kk * 32 + (lane >> 4) * 16;
        const int bkoff = kk * 32 + ((lane >> 3) & 1) * 16;
        #pragma unroll
        for (int m = 0; m < 2; m++) {
            uint32_t off = SWZ128((uint32_t)((mrow + m * 16 + arowoff) * 128 + akoff));
            ldsm4(ah[m], aT + off);
        }
        {
            uint32_t off = SWZ128((uint32_t)((nbase + nrowoff) * 128 + bkoff));
            ldsm4(bw, bW + off);
        }
        #pragma unroll
        for (int m = 0; m < 2; m++) {
            mma16816h(acc[m * 2],     ah[m], bw[0], bw[1]);
            mma16816h(acc[m * 2 + 1], ah[m], bw[2], bw[3]);
        }
    }
}

// ---------------------------------------------------------------------------
// Prep kernels (device symbols bound in device code — R3 lesson).
// ---------------------------------------------------------------------------
__global__ void split_kernel(const float* __restrict__ src, int which, size_t n) {
    size_t stride = (size_t)gridDim.x * blockDim.x;
    if (which == 2) {   // Whh -> single fp16
        for (size_t i = (size_t)blockIdx.x * blockDim.x + threadIdx.x; i < n; i += stride)
            g_Whh_f16[i] = __float2half(src[i]);
        return;
    }
    __nv_bfloat16* hi = (which == 0) ? g_x_hi : g_Wih_hi;
    __nv_bfloat16* lo = (which == 0) ? g_x_lo : g_Wih_lo;
    for (size_t i = (size_t)blockIdx.x * blockDim.x + threadIdx.x; i < n; i += stride) {
        float v = src[i];
        __nv_bfloat16 h = __float2bfloat16(v);
        hi[i] = h;
        lo[i] = __float2bfloat16(v - __bfloat162float(h));
    }
}

__global__ void init_state_kernel() {
    int i = blockIdx.x * blockDim.x + threadIdx.x;
    if (i == 0) g_bar = 0u;
    if (i < Bv * Hv) {
        g_h[0][i] = __float2half(0.0f);
    }
}

// ---------------------------------------------------------------------------
// Input GEMM (bf16 HMMA 3-pass, unchanged from R4-R9 pass)
// ---------------------------------------------------------------------------
#define G_STAGE 65536
#define G_SMEM  (2 * G_STAGE)

__device__ __forceinline__ void gemm_load(uint32_t sb, int s, int k0,
                                          int m0, int n0, int tid) {
    uint32_t base = sb + (uint32_t)s * G_STAGE;
    #pragma unroll
    for (int r = 0; r < 8; r++) {
        int idx = tid + r * 256;
        int hf = idx >> 10, rem = idx & 1023;
        int row = rem >> 3, c = rem & 7;
        const __nv_bfloat16* src = (hf ? g_x_lo : g_x_hi)
                                   + (size_t)(m0 + row) * Iv + k0 + c * 8;
        cp16(base + hf * 16384 + SWZ128((uint32_t)(row * 128 + c * 16)), src);
    }
    #pragma unroll
    for (int r = 0; r < 8; r++) {
        int idx = tid + r * 256;
        int hf = idx >> 10, rem = idx & 1023;
        int row = rem >> 3, c = rem & 7;
        const __nv_bfloat16* src = (hf ? g_Wih_lo : g_Wih_hi)
                                   + (size_t)(n0 + row) * Iv + k0 + c * 8;
        cp16(base + 32768 + hf * 16384 + SWZ128((uint32_t)(row * 128 + c * 16)), src);
    }
}

__global__ void __launch_bounds__(256, 1) gemm_in_mma(const float* __restrict__ bias)
{
    extern __shared__ char smem[];
    uint32_t sb = smem_u32(smem);
    const int tid = threadIdx.x, lane = tid & 31, wid = tid >> 5;
    const int m0 = blockIdx.y * 128, n0 = blockIdx.x * 128;

    float acc[16][4];
    #pragma unroll
    for (int i = 0; i < 16; i++)
        #pragma unroll
        for (int j = 0; j < 4; j++) acc[i][j] = 0.0f;

    gemm_load(sb, 0, 0, m0, n0, tid);
    CP_COMMIT();

    const int mrow = (wid & 3) * 32, nbase = (wid >> 2) * 64;
    for (int it = 0; it < 16; it++) {
        const int s = it & 1;
        if (it + 1 < 16) {
            gemm_load(sb, (it + 1) & 1, (it + 1) * 64, m0, n0, tid);
            CP_COMMIT();
            CP_WAIT(1);
        } else {
            CP_WAIT(0);
        }
        __syncthreads();
        uint32_t base = sb + (uint32_t)s * G_STAGE;
        warp_mma_chunk<4>(base, base + 16384, base + 32768, base + 49152,
                          mrow, nbase, lane, acc);
        __syncthreads();
    }

    #pragma unroll
    for (int m = 0; m < 2; m++)
        #pragma unroll
        for (int j = 0; j < 8; j++) {
            float* a = acc[m * 8 + j];
            int gr = m0 + (wid & 3) * 32 + m * 16 + (lane >> 2);
            int n  = n0 + (wid >> 2) * 64 + j * 8 + 2 * (lane & 3);
            float b0 = bias[n], b1 = bias[n + 1];
            int bi0 = gr >> 9, tt0 = gr & 511;
            float* o0 = g_Gx + ((size_t)tt0 * Bv + bi0) * Gv + n;
            o0[0] = a[0] + b0; o0[1] = a[1] + b1;
            int gr2 = gr + 8, bi2 = gr2 >> 9, tt2 = gr2 & 511;
            float* o2 = g_Gx + ((size_t)tt2 * Bv + bi2) * Gv + n;
            o2[0] = a[2] + b0; o2[1] = a[3] + b1;
        }
}

// ---------------------------------------------------------------------------
// Persistent LSTM recurrence (fp16 single-pass, R9 pacing + R11 deltas):
// 4 A-buffers / lookahead-3; Gx double-buffered, prefetched during the
// previous step's barrier spin; cell state c resident in SMEM; dout writes
// moved after the barrier arrival. 128 CTAs x 256 threads, 1 CTA/SM.
// ---------------------------------------------------------------------------
#define WS     0                           /* 16 sub-chunks x 4KB = 64KB */
#define AB     65536                       /* 4 chunk buffers x 16KB = 64KB */
#define GXS    (AB + 4 * 16384)            /* 131072: 2 x 9216 */
#define CS     (GXS + 2 * 9216)            /* 149504: 512 fp32 = 2KB */
#define GS0    (CS + 2048)                 /* 151552: 64 x 33 fp32 = 8448 */
#define GS1    (GS0 + 8448)                /* 160000 */
#define P_SMEM (GS1 + 8448)                /* 168448 (~164.5KB) */

// Load A tile for K-chunk of 128 (two 64-wide sub-tiles, 16KB total).
__device__ __forceinline__ void persist_loadA(uint32_t sb, int st, int k0,
                                              const __half* __restrict__ hIn,
                                              int tid) {
    uint32_t base = sb + AB + (uint32_t)st * 16384;
    #pragma unroll
    for (int r = 0; r < 4; r++) {          // 1024 cp16 = 16KB
        int idx = tid + r * 256;
        int sub = idx >> 9, rem = idx & 511;
        int row = rem >> 3, c = rem & 7;   // row = batch 0..63
        const __half* src = hIn + (size_t)row * Hv + k0 + sub * 64 + c * 8;
        cp16(base + sub * 8192 + SWZ128((uint32_t)(row * 128 + c * 16)), src);
    }
}

// Prefetch the Gx gate slice for step t into buffer buf (own commit group).
__device__ __forceinline__ void load_gx(uint32_t sb, int buf, int t, int j0,
                                        int tid) {
    const float* gxbase = g_Gx + ((size_t)t * Bv) * Gv + j0;
    uint32_t dst = sb + GXS + (uint32_t)buf * 9216;
    #pragma unroll
    for (int r = 0; r < 2; r++) {          // 512 cp16 = 8KB (row stride 144B)
        int idx = tid + r * 256;
        int b = idx >> 3;
        int gate = (idx >> 1) & 3, hf = idx & 1;
        cp16(dst + (uint32_t)(b * 144 + gate * 32 + hf * 16),
             gxbase + (size_t)b * Gv + gate * Hv + hf * 4);
    }
    CP_COMMIT();
}

__global__ void __launch_bounds__(256, 1) lstm_persistent(float* __restrict__ dout)
{
    extern __shared__ char smem[];
    uint32_t sb = smem_u32(smem);
    const int tid = threadIdx.x, lane = tid & 31, wid = tid >> 5;
    const int j0 = blockIdx.x * 8;
    const int par = wid >> 2;                  // chunk parity this warp computes
    const int mrow = (wid & 1) * 32;
    const int nbase = ((wid >> 1) & 1) * 16;

    // ---- Preload W_f16 tile: 32 gate rows x K=1024 = 64KB, sub-chunk-major
    #pragma unroll
    for (int r = 0; r < 16; r++) {             // 4096 cp16
        int idx = tid + r * 256;
        int chunk = idx >> 8, within = idx & 255;
        int row = within >> 3, c = within & 7;
        int gate = row >> 3, jc = row & 7;
        const __half* src = g_Whh_f16
            + (size_t)(gate * Hv + j0 + jc) * Hv + chunk * 64 + c * 8;
        cp16(sb + WS + chunk * 4096 + SWZ128((uint32_t)(row * 128 + c * 16)), src);
    }
    CP_COMMIT();
    CP_WAIT(0);
    __syncthreads();

    float* Gs0 = (float*)(smem + GS0);
    float* Gs1 = (float*)(smem + GS1);
    float* cs  = (float*)(smem + CS);

    // cell state resident in SMEM (each thread owns cells tid, tid+256)
    cs[tid] = 0.0f;
    cs[tid + 256] = 0.0f;

    // prefetch Gx(0) (own group — drained by the it=0 wait of step 0)
    load_gx(sb, 0, 0, j0, tid);

    for (int t = 0; t < Tv; t++) {
        const __half* hIn = g_h[t & 1];
        __half* hOut      = g_h[(t + 1) & 1];

        float acc[4][4];
        #pragma unroll
        for (int i = 0; i < 4; i++)
            #pragma unroll
            for (int j = 0; j < 4; j++) acc[i][j] = 0.0f;

        // prologue: chunks 0,1,2 (lookahead 3)
        persist_loadA(sb, 0, 0,   hIn, tid); CP_COMMIT();
        persist_loadA(sb, 1, 128, hIn, tid); CP_COMMIT();
        persist_loadA(sb, 2, 256, hIn, tid); CP_COMMIT();

        for (int it = 0; it < 8; it++) {
            if      (it <= 5) CP_WAIT(2);   // drains chunk it (+ Gx at it=0)
            else if (it == 6) CP_WAIT(1);
            else              CP_WAIT(0);
            __syncthreads();
            if ((it & 1) == par) {
                uint32_t aT = sb + AB + (uint32_t)(it & 3) * 16384;
                warp_mma_1p(aT,        sb + WS + (uint32_t)(2 * it) * 4096,
                            mrow, nbase, lane, acc);
                warp_mma_1p(aT + 8192, sb + WS + (uint32_t)(2 * it + 1) * 4096,
                            mrow, nbase, lane, acc);
            }
            if (it + 3 < 8) {
                persist_loadA(sb, (it + 3) & 3, (it + 3) * 128, hIn, tid);
                CP_COMMIT();
            }
        }

        // Stage partial gates (per k-parity buffer)
        float* Gs = par ? Gs1 : Gs0;
        #pragma unroll
        for (int m = 0; m < 2; m++)
            #pragma unroll
            for (int p = 0; p < 2; p++) {
                float* a = acc[m * 2 + p];
                int r0 = mrow + m * 16 + (lane >> 2);
                int cc = nbase + p * 8 + 2 * (lane & 3);
                Gs[r0 * 33 + cc]           = a[0];
                Gs[r0 * 33 + cc + 1]       = a[1];
                Gs[(r0 + 8) * 33 + cc]     = a[2];
                Gs[(r0 + 8) * 33 + cc + 1] = a[3];
            }
        __syncthreads();

        // Fused cell update: h written now; dout deferred past the arrival
        const float* gx = (float*)(smem + GXS + (uint32_t)(t & 1) * 9216);
        float hn_s[2], cn_s[2];
        #pragma unroll
        for (int p = 0; p < 2; p++) {
            int cell = tid + p * 256;
            int b = cell >> 3, jc = cell & 7;
            const float* gxr = gx + b * 36;
            float gi = Gs0[b * 33 + jc]      + Gs1[b * 33 + jc]      + gxr[jc];
            float gf = Gs0[b * 33 + 8 + jc]  + Gs1[b * 33 + 8 + jc]  + gxr[8 + jc];
            float gg = Gs0[b * 33 + 16 + jc] + Gs1[b * 33 + 16 + jc] + gxr[16 + jc];
            float go = Gs0[b * 33 + 24 + jc] + Gs1[b * 33 + 24 + jc] + gxr[24 + jc];

            float c_old = cs[cell];
            float cn = sigm(gf) * c_old + sigm(gi) * tanh_fast(gg);
            float hn = sigm(go) * tanh_fast(cn);
            cs[cell] = cn;
            hn_s[p] = hn; cn_s[p] = cn;

            hOut[b * Hv + j0 + jc] = __float2half(hn);
        }
        __syncthreads();

        // prefetch next step's Gx during the barrier window
        if (t + 1 < Tv) load_gx(sb, (t + 1) & 1, t + 1, j0, tid);

        // arrive: h(t+1) published
        if (tid == 0) {
            unsigned int ignored;
            asm volatile("atom.add.release.gpu.u32 %0, [%1], 1;"
                         : "=r"(ignored) : "l"(&g_bar) : "memory");
        }

        // off-critical-path: stream outputs to DRAM
        #pragma unroll
        for (int p = 0; p < 2; p++) {
            int cell = tid + p * 256;
            int b = cell >> 3, jc = cell & 7;
            dout[(size_t)b * Tv * Hv + (size_t)t * Hv + j0 + jc] = hn_s[p];
            if (t == Tv - 1) {
                size_t obase = (size_t)Bv * Tv * Hv;
                int hidx = b * Hv + j0 + jc;
                dout[obase + hidx] = hn_s[p];                    // h_T
                dout[obase + (size_t)Bv * Hv + hidx] = cn_s[p];  // c_T
            }
        }

        // spin for all arrivals of step t
        if (tid == 0) {
            unsigned int target = 128u * (unsigned int)(t + 1);
            unsigned int cur;
            do {
                asm volatile("ld.acquire.gpu.u32 %0, [%1];"
                             : "=r"(cur) : "l"(&g_bar) : "memory");
                if (cur >= target) break;
                asm volatile("nanosleep.u32 16;");
            } while (true);
        }
        __syncthreads();
    }
}

// ---------------------------------------------------------------------------
// Launch
// ---------------------------------------------------------------------------
extern "C" void kernel_launch(void* const* d_in, const int* in_sizes, int n_in,
                              void* d_out, int out_size)
{
    const float* x    = (const float*)d_in[0];  // [B, T, I]
    const float* Wih  = (const float*)d_in[1];  // [4H, I]
    const float* Whh  = (const float*)d_in[2];  // [4H, H]
    const float* bias = (const float*)d_in[3];  // [4H]
    float* out = (float*)d_out;
    (void)in_sizes; (void)n_in; (void)out_size;

    cudaFuncSetAttribute(gemm_in_mma,     cudaFuncAttributeMaxDynamicSharedMemorySize, G_SMEM);
    cudaFuncSetAttribute(lstm_persistent, cudaFuncAttributeMaxDynamicSharedMemorySize, P_SMEM);

    split_kernel<<<8192, 256>>>(x,   0, (size_t)Bv * Tv * Iv);
    split_kernel<<<4096, 256>>>(Wih, 1, (size_t)Gv * Iv);
    split_kernel<<<4096, 256>>>(Whh, 2, (size_t)Gv * Hv);
    init_state_kernel<<<(Bv * Hv + 255) / 256, 256>>>();

    dim3 ggrid(Gv / 128, (Bv * Tv) / 128);   // (32, 256)
    gemm_in_mma<<<ggrid, 256, G_SMEM>>>(bias);

    lstm_persistent<<<128, 256, P_SMEM>>>(out);
}

// round 12
// speedup vs baseline: 1.9074x; 1.3229x over previous
#include <cuda_runtime.h>
#include <cuda_bf16.h>
#include <cuda_fp16.h>
#include <cstdint>
#include <math.h>

#define Bv 64
#define Tv 512
#define Iv 1024
#define Hv 1024
#define Gv 4096   // 4*H

// ---------------------------------------------------------------------------
// Static device scratch (all fp16 now)
// ---------------------------------------------------------------------------
__device__ __half g_Gx[(size_t)Tv * Bv * Gv];             // 256MB [T][B][4H]
__device__ __half g_x_f16[(size_t)Bv * Tv * Iv];          // 64MB
__device__ __half g_Wih_f16[(size_t)Gv * Iv];             // 8MB
__device__ __half g_Whh_f16[(size_t)Gv * Hv];             // 8MB
__device__ __half g_h[2][Bv * Hv];                        // fp16 h
__device__ unsigned int g_bar;

// ---------------------------------------------------------------------------
// Helpers
// ---------------------------------------------------------------------------
__device__ __forceinline__ uint32_t smem_u32(const void* p) {
    uint32_t a;
    asm("{ .reg .u64 t; cvta.to.shared.u64 t, %1; cvt.u32.u64 %0, t; }"
        : "=r"(a) : "l"(p));
    return a;
}

#define SWZ128(o) ((o) ^ (((o) >> 3) & 0x70))

__device__ __forceinline__ void cp16(uint32_t dst, const void* src) {
    asm volatile("cp.async.cg.shared.global [%0], [%1], 16;" :: "r"(dst), "l"(src));
}
#define CP_COMMIT() asm volatile("cp.async.commit_group;" ::: "memory")
#define CP_WAIT(n)  asm volatile("cp.async.wait_group %0;" :: "n"(n) : "memory")

__device__ __forceinline__ void ldsm4(uint32_t* r, uint32_t addr) {
    asm volatile("ldmatrix.sync.aligned.m8n8.x4.shared.b16 {%0,%1,%2,%3}, [%4];"
        : "=r"(r[0]), "=r"(r[1]), "=r"(r[2]), "=r"(r[3]) : "r"(addr));
}

__device__ __forceinline__ void mma16816h(float* d, const uint32_t* a,
                                          uint32_t b0, uint32_t b1) {
    asm volatile(
        "mma.sync.aligned.m16n8k16.row.col.f32.f16.f16.f32 "
        "{%0,%1,%2,%3}, {%4,%5,%6,%7}, {%8,%9}, {%0,%1,%2,%3};"
        : "+f"(d[0]), "+f"(d[1]), "+f"(d[2]), "+f"(d[3])
        : "r"(a[0]), "r"(a[1]), "r"(a[2]), "r"(a[3]), "r"(b0), "r"(b1));
}

__device__ __forceinline__ float sigm(float x) {
    return 1.0f / (1.0f + __expf(-x));
}
__device__ __forceinline__ float tanh_fast(float x) {
    float cx = fminf(fmaxf(x, -10.0f), 10.0f);
    float e = __expf(2.0f * cx);
    return (e - 1.0f) / (e + 1.0f);
}

// ---------------------------------------------------------------------------
// fp16 single-pass warp MMA over one 64-wide K sub-tile, NT n-tiles of 16.
// acc layout: acc[m*2*NT + jb*2 + p][4]
// ---------------------------------------------------------------------------
template <int NT>
__device__ __forceinline__ void warp_mma_f16(
    uint32_t aT, uint32_t bT, int mrow, int nbase, int lane, float acc[][4])
{
    const int arowoff = (lane & 7) + ((lane >> 3) & 1) * 8;
    const int nrowoff = (lane & 7) + ((lane >> 4) & 1) * 8;
    #pragma unroll
    for (int kk = 0; kk < 4; kk++) {
        uint32_t ah[2][4], bw[NT][4];
        const int akoff = kk * 32 + (lane >> 4) * 16;
        const int bkoff = kk * 32 + ((lane >> 3) & 1) * 16;
        #pragma unroll
        for (int m = 0; m < 2; m++) {
            uint32_t off = SWZ128((uint32_t)((mrow + m * 16 + arowoff) * 128 + akoff));
            ldsm4(ah[m], aT + off);
        }
        #pragma unroll
        for (int jb = 0; jb < NT; jb++) {
            uint32_t off = SWZ128((uint32_t)((nbase + jb * 16 + nrowoff) * 128 + bkoff));
            ldsm4(bw[jb], bT + off);
        }
        #pragma unroll
        for (int jb = 0; jb < NT; jb++)
            #pragma unroll
            for (int m = 0; m < 2; m++) {
                mma16816h(acc[m * 2 * NT + jb * 2],     ah[m], bw[jb][0], bw[jb][1]);
                mma16816h(acc[m * 2 * NT + jb * 2 + 1], ah[m], bw[jb][2], bw[jb][3]);
            }
    }
}

// ---------------------------------------------------------------------------
// Fused prep: fp32 -> fp16 conversions + state init (device symbols bound in
// device code — R3 lesson).
// ---------------------------------------------------------------------------
__global__ void prep_all(const float* __restrict__ x,
                         const float* __restrict__ Wih,
                         const float* __restrict__ Whh) {
    const size_t NX = (size_t)Bv * Tv * Iv;   // 33.5M
    const size_t NW = (size_t)Gv * Iv;        // 4.2M
    size_t gid = (size_t)blockIdx.x * blockDim.x + threadIdx.x;
    size_t stride = (size_t)gridDim.x * blockDim.x;
    for (size_t i = gid; i < NX; i += stride) g_x_f16[i]   = __float2half(x[i]);
    for (size_t i = gid; i < NW; i += stride) g_Wih_f16[i] = __float2half(Wih[i]);
    for (size_t i = gid; i < NW; i += stride) g_Whh_f16[i] = __float2half(Whh[i]);
    for (size_t i = gid; i < (size_t)Bv * Hv; i += stride) g_h[0][i] = __float2half(0.0f);
    if (gid == 0) g_bar = 0u;
}

__global__ void dummy_kernel() {}

// ---------------------------------------------------------------------------
// Input GEMM (fp16 single-pass HMMA): Gx[t][b][n] = x[b,t,:] . Wih[n,:] + b[n]
// CTA tile 128x128, 8 warps (4m x 2n), warp m32 x n64. K=1024, chunks of 64.
// ---------------------------------------------------------------------------
#define G_STAGE 32768
#define G_SMEM  (2 * G_STAGE)

__device__ __forceinline__ void gemm_load(uint32_t sb, int s, int k0,
                                          int m0, int n0, int tid) {
    uint32_t base = sb + (uint32_t)s * G_STAGE;
    #pragma unroll
    for (int r = 0; r < 4; r++) {           // A: 1024 cp16 = 16KB
        int idx = tid + r * 256;
        int row = idx >> 3, c = idx & 7;
        cp16(base + SWZ128((uint32_t)(row * 128 + c * 16)),
             g_x_f16 + (size_t)(m0 + row) * Iv + k0 + c * 8);
    }
    #pragma unroll
    for (int r = 0; r < 4; r++) {           // B: 1024 cp16 = 16KB
        int idx = tid + r * 256;
        int row = idx >> 3, c = idx & 7;
        cp16(base + 16384 + SWZ128((uint32_t)(row * 128 + c * 16)),
             g_Wih_f16 + (size_t)(n0 + row) * Iv + k0 + c * 8);
    }
}

__global__ void __launch_bounds__(256, 1) gemm_in_mma(const float* __restrict__ bias)
{
    extern __shared__ char smem[];
    uint32_t sb = smem_u32(smem);
    const int tid = threadIdx.x, lane = tid & 31, wid = tid >> 5;
    const int m0 = blockIdx.y * 128, n0 = blockIdx.x * 128;

    float acc[16][4];
    #pragma unroll
    for (int i = 0; i < 16; i++)
        #pragma unroll
        for (int j = 0; j < 4; j++) acc[i][j] = 0.0f;

    gemm_load(sb, 0, 0, m0, n0, tid);
    CP_COMMIT();

    const int mrow = (wid & 3) * 32, nbase = (wid >> 2) * 64;
    for (int it = 0; it < 16; it++) {
        const int s = it & 1;
        if (it + 1 < 16) {
            gemm_load(sb, (it + 1) & 1, (it + 1) * 64, m0, n0, tid);
            CP_COMMIT();
            CP_WAIT(1);
        } else {
            CP_WAIT(0);
        }
        __syncthreads();
        uint32_t base = sb + (uint32_t)s * G_STAGE;
        warp_mma_f16<4>(base, base + 16384, mrow, nbase, lane, acc);
        __syncthreads();
    }

    // Epilogue: remap rows to [T][B][4H] fp16, add bias.
    #pragma unroll
    for (int m = 0; m < 2; m++)
        #pragma unroll
        for (int j = 0; j < 8; j++) {
            float* a = acc[m * 8 + j];
            int gr = m0 + (wid & 3) * 32 + m * 16 + (lane >> 2);
            int n  = n0 + (wid >> 2) * 64 + j * 8 + 2 * (lane & 3);
            float b0 = bias[n], b1 = bias[n + 1];
            int bi0 = gr >> 9, tt0 = gr & 511;
            __half2* o0 = (__half2*)(g_Gx + ((size_t)tt0 * Bv + bi0) * Gv + n);
            *o0 = __floats2half2_rn(a[0] + b0, a[1] + b1);
            int gr2 = gr + 8, bi2 = gr2 >> 9, tt2 = gr2 & 511;
            __half2* o2 = (__half2*)(g_Gx + ((size_t)tt2 * Bv + bi2) * Gv + n);
            *o2 = __floats2half2_rn(a[2] + b0, a[3] + b1);
        }
}

// ---------------------------------------------------------------------------
// Persistent LSTM recurrence (fp16 single-pass). 128 CTAs x 256 threads.
// CTA owns 8 hidden cols (32 gate rows). W_f16 (64KB) SMEM-resident.
// 5 A-buffers, lookahead-4 paced issue; Gx fp16 double-buffered, prefetched
// during the previous step's barrier spin; c in SMEM; dout after arrival.
// ---------------------------------------------------------------------------
#define WS     0                           /* 16 sub-chunks x 4KB = 64KB */
#define AB     65536                       /* 5 chunk buffers x 16KB = 80KB */
#define GXS    (AB + 5 * 16384)            /* 147456: 2 x 5120 (fp16, 80B/row) */
#define CS     (GXS + 2 * 5120)            /* 157696: 512 fp32 = 2KB */
#define GS0    (CS + 2048)                 /* 159744: 64 x 33 fp32 = 8448 */
#define GS1    (GS0 + 8448)                /* 168192 */
#define P_SMEM (GS1 + 8448)                /* 176640 (~172.5KB) */

// Load A tile for K-chunk of 128 (two 64-wide sub-tiles, 16KB total).
__device__ __forceinline__ void persist_loadA(uint32_t sb, int st, int k0,
                                              const __half* __restrict__ hIn,
                                              int tid) {
    uint32_t base = sb + AB + (uint32_t)st * 16384;
    #pragma unroll
    for (int r = 0; r < 4; r++) {          // 1024 cp16 = 16KB
        int idx = tid + r * 256;
        int sub = idx >> 9, rem = idx & 511;
        int row = rem >> 3, c = rem & 7;   // row = batch 0..63
        const __half* src = hIn + (size_t)row * Hv + k0 + sub * 64 + c * 8;
        cp16(base + sub * 8192 + SWZ128((uint32_t)(row * 128 + c * 16)), src);
    }
}

// Prefetch the fp16 Gx gate slice for step t into buffer buf (own group).
__device__ __forceinline__ void load_gx(uint32_t sb, int buf, int t, int j0,
                                        int tid) {
    const __half* gxbase = g_Gx + ((size_t)t * Bv) * Gv + j0;
    uint32_t dst = sb + GXS + (uint32_t)buf * 5120;
    if (tid < 256) {                       // 256 cp16 = 4KB (row stride 80B)
        int b = tid >> 2, gate = tid & 3;
        cp16(dst + (uint32_t)(b * 80 + gate * 16),
             gxbase + (size_t)b * Gv + gate * Hv);
    }
    CP_COMMIT();
}

__global__ void __launch_bounds__(256, 1) lstm_persistent(float* __restrict__ dout)
{
    extern __shared__ char smem[];
    uint32_t sb = smem_u32(smem);
    const int tid = threadIdx.x, lane = tid & 31, wid = tid >> 5;
    const int j0 = blockIdx.x * 8;
    const int par = wid >> 2;                  // chunk parity this warp computes
    const int mrow = (wid & 1) * 32;
    const int nbase = ((wid >> 1) & 1) * 16;

    // ---- Preload W_f16 tile: 32 gate rows x K=1024 = 64KB, sub-chunk-major
    #pragma unroll
    for (int r = 0; r < 16; r++) {             // 4096 cp16
        int idx = tid + r * 256;
        int chunk = idx >> 8, within = idx & 255;
        int row = within >> 3, c = within & 7;
        int gate = row >> 3, jc = row & 7;
        const __half* src = g_Whh_f16
            + (size_t)(gate * Hv + j0 + jc) * Hv + chunk * 64 + c * 8;
        cp16(sb + WS + chunk * 4096 + SWZ128((uint32_t)(row * 128 + c * 16)), src);
    }
    CP_COMMIT();
    CP_WAIT(0);
    __syncthreads();

    float* Gs0 = (float*)(smem + GS0);
    float* Gs1 = (float*)(smem + GS1);
    float* cs  = (float*)(smem + CS);
    cs[tid] = 0.0f;
    cs[tid + 256] = 0.0f;

    // prefetch Gx(0) (own group — drained by the it=0 wait of step 0)
    load_gx(sb, 0, 0, j0, tid);

    for (int t = 0; t < Tv; t++) {
        const __half* hIn = g_h[t & 1];
        __half* hOut      = g_h[(t + 1) & 1];

        float acc[4][4];
        #pragma unroll
        for (int i = 0; i < 4; i++)
            #pragma unroll
            for (int j = 0; j < 4; j++) acc[i][j] = 0.0f;

        // prologue: chunks 0-3 (lookahead 4, 5 buffers)
        persist_loadA(sb, 0, 0,   hIn, tid); CP_COMMIT();
        persist_loadA(sb, 1, 128, hIn, tid); CP_COMMIT();
        persist_loadA(sb, 2, 256, hIn, tid); CP_COMMIT();
        persist_loadA(sb, 3, 384, hIn, tid); CP_COMMIT();

        for (int it = 0; it < 8; it++) {
            // pending at it=0: {Gx, A0..A3}; WAIT(3) completes Gx+A0.
            if      (it <= 4) CP_WAIT(3);
            else if (it == 5) CP_WAIT(2);
            else if (it == 6) CP_WAIT(1);
            else              CP_WAIT(0);
            __syncthreads();
            if ((it & 1) == par) {
                uint32_t aT = sb + AB + (uint32_t)(it % 5) * 16384;
                warp_mma_f16<1>(aT,        sb + WS + (uint32_t)(2 * it) * 4096,
                                mrow, nbase, lane, acc);
                warp_mma_f16<1>(aT + 8192, sb + WS + (uint32_t)(2 * it + 1) * 4096,
                                mrow, nbase, lane, acc);
            }
            if (it + 4 < 8) {
                persist_loadA(sb, (it + 4) % 5, (it + 4) * 128, hIn, tid);
                CP_COMMIT();
            }
        }

        // Stage partial gates (per k-parity buffer)
        float* Gs = par ? Gs1 : Gs0;
        #pragma unroll
        for (int m = 0; m < 2; m++)
            #pragma unroll
            for (int p = 0; p < 2; p++) {
                float* a = acc[m * 2 + p];
                int r0 = mrow + m * 16 + (lane >> 2);
                int cc = nbase + p * 8 + 2 * (lane & 3);
                Gs[r0 * 33 + cc]           = a[0];
                Gs[r0 * 33 + cc + 1]       = a[1];
                Gs[(r0 + 8) * 33 + cc]     = a[2];
                Gs[(r0 + 8) * 33 + cc + 1] = a[3];
            }
        __syncthreads();

        // Fused cell update: h written now; dout deferred past the arrival
        const __half* gx = (const __half*)(smem + GXS + (uint32_t)(t & 1) * 5120);
        float hn_s[2], cn_s[2];
        #pragma unroll
        for (int p = 0; p < 2; p++) {
            int cell = tid + p * 256;
            int b = cell >> 3, jc = cell & 7;
            const __half* gxr = gx + b * 40;
            float gi = Gs0[b * 33 + jc]      + Gs1[b * 33 + jc]      + __half2float(gxr[jc]);
            float gf = Gs0[b * 33 + 8 + jc]  + Gs1[b * 33 + 8 + jc]  + __half2float(gxr[8 + jc]);
            float gg = Gs0[b * 33 + 16 + jc] + Gs1[b * 33 + 16 + jc] + __half2float(gxr[16 + jc]);
            float go = Gs0[b * 33 + 24 + jc] + Gs1[b * 33 + 24 + jc] + __half2float(gxr[24 + jc]);

            float c_old = cs[cell];
            float cn = sigm(gf) * c_old + sigm(gi) * tanh_fast(gg);
            float hn = sigm(go) * tanh_fast(cn);
            cs[cell] = cn;
            hn_s[p] = hn; cn_s[p] = cn;

            hOut[b * Hv + j0 + jc] = __float2half(hn);
        }
        __syncthreads();

        // prefetch next step's Gx during the barrier window
        if (t + 1 < Tv) load_gx(sb, (t + 1) & 1, t + 1, j0, tid);

        // arrive: h(t+1) published
        if (tid == 0) {
            unsigned int ignored;
            asm volatile("atom.add.release.gpu.u32 %0, [%1], 1;"
                         : "=r"(ignored) : "l"(&g_bar) : "memory");
        }

        // off-critical-path: stream outputs to DRAM
        #pragma unroll
        for (int p = 0; p < 2; p++) {
            int cell = tid + p * 256;
            int b = cell >> 3, jc = cell & 7;
            dout[(size_t)b * Tv * Hv + (size_t)t * Hv + j0 + jc] = hn_s[p];
            if (t == Tv - 1) {
                size_t obase = (size_t)Bv * Tv * Hv;
                int hidx = b * Hv + j0 + jc;
                dout[obase + hidx] = hn_s[p];                    // h_T
                dout[obase + (size_t)Bv * Hv + hidx] = cn_s[p];  // c_T
            }
        }

        // spin for all arrivals of step t
        if (tid == 0) {
            unsigned int target = 128u * (unsigned int)(t + 1);
            unsigned int cur;
            do {
                asm volatile("ld.acquire.gpu.u32 %0, [%1];"
                             : "=r"(cur) : "l"(&g_bar) : "memory");
                if (cur >= target) break;
                asm volatile("nanosleep.u32 16;");
            } while (true);
        }
        __syncthreads();
    }
}

// ---------------------------------------------------------------------------
// Launch: prep_all(1), gemm(2), dummy(3), persistent(4)
// (harness prepends 2 launches; ncu -s 5 -c 1 then captures lstm_persistent)
// ---------------------------------------------------------------------------
extern "C" void kernel_launch(void* const* d_in, const int* in_sizes, int n_in,
                              void* d_out, int out_size)
{
    const float* x    = (const float*)d_in[0];  // [B, T, I]
    const float* Wih  = (const float*)d_in[1];  // [4H, I]
    const float* Whh  = (const float*)d_in[2];  // [4H, H]
    const float* bias = (const float*)d_in[3];  // [4H]
    float* out = (float*)d_out;
    (void)in_sizes; (void)n_in; (void)out_size;

    cudaFuncSetAttribute(gemm_in_mma,     cudaFuncAttributeMaxDynamicSharedMemorySize, G_SMEM);
    cudaFuncSetAttribute(lstm_persistent, cudaFuncAttributeMaxDynamicSharedMemorySize, P_SMEM);

    prep_all<<<4096, 256>>>(x, Wih, Whh);

    dim3 ggrid(Gv / 128, (Bv * Tv) / 128);   // (32, 256)
    gemm_in_mma<<<ggrid, 256, G_SMEM>>>(bias);

    dummy_kernel<<<1, 32>>>();

    lstm_persistent<<<128, 256, P_SMEM>>>(out);
}

// round 13
// speedup vs baseline: 2.0957x; 1.0987x over previous
#include <cuda_runtime.h>
#include <cuda_bf16.h>
#include <cuda_fp16.h>
#include <cstdint>
#include <math.h>

#define Bv 64
#define Tv 512
#define Iv 1024
#define Hv 1024
#define Gv 4096   // 4*H

// ---------------------------------------------------------------------------
// Static device scratch (all fp16)
// ---------------------------------------------------------------------------
__device__ __half g_Gx[(size_t)Tv * Bv * Gv];             // 256MB [T][B][4H]
__device__ __half g_x_f16[(size_t)Bv * Tv * Iv];          // 64MB
__device__ __half g_Wih_f16[(size_t)Gv * Iv];             // 8MB
__device__ __half g_Whh_f16[(size_t)Gv * Hv];             // 8MB
__device__ __half g_h[2][Bv * Hv];                        // fp16 h
__device__ unsigned int g_bar;

// ---------------------------------------------------------------------------
// Helpers
// ---------------------------------------------------------------------------
__device__ __forceinline__ uint32_t smem_u32(const void* p) {
    uint32_t a;
    asm("{ .reg .u64 t; cvta.to.shared.u64 t, %1; cvt.u32.u64 %0, t; }"
        : "=r"(a) : "l"(p));
    return a;
}

#define SWZ128(o) ((o) ^ (((o) >> 3) & 0x70))

__device__ __forceinline__ void cp16(uint32_t dst, const void* src) {
    asm volatile("cp.async.cg.shared.global [%0], [%1], 16;" :: "r"(dst), "l"(src));
}
#define CP_COMMIT() asm volatile("cp.async.commit_group;" ::: "memory")
#define CP_WAIT(n)  asm volatile("cp.async.wait_group %0;" :: "n"(n) : "memory")

__device__ __forceinline__ void ldsm4(uint32_t* r, uint32_t addr) {
    asm volatile("ldmatrix.sync.aligned.m8n8.x4.shared.b16 {%0,%1,%2,%3}, [%4];"
        : "=r"(r[0]), "=r"(r[1]), "=r"(r[2]), "=r"(r[3]) : "r"(addr));
}

__device__ __forceinline__ void mma16816h(float* d, const uint32_t* a,
                                          uint32_t b0, uint32_t b1) {
    asm volatile(
        "mma.sync.aligned.m16n8k16.row.col.f32.f16.f16.f32 "
        "{%0,%1,%2,%3}, {%4,%5,%6,%7}, {%8,%9}, {%0,%1,%2,%3};"
        : "+f"(d[0]), "+f"(d[1]), "+f"(d[2]), "+f"(d[3])
        : "r"(a[0]), "r"(a[1]), "r"(a[2]), "r"(a[3]), "r"(b0), "r"(b1));
}

__device__ __forceinline__ float sigm(float x) {
    return 1.0f / (1.0f + __expf(-x));
}
__device__ __forceinline__ float tanh_fast(float x) {
    float cx = fminf(fmaxf(x, -10.0f), 10.0f);
    float e = __expf(2.0f * cx);
    return (e - 1.0f) / (e + 1.0f);
}

// ---------------------------------------------------------------------------
// fp16 single-pass warp MMA over one 64-wide K sub-tile, NT n-tiles of 16.
// ---------------------------------------------------------------------------
template <int NT>
__device__ __forceinline__ void warp_mma_f16(
    uint32_t aT, uint32_t bT, int mrow, int nbase, int lane, float acc[][4])
{
    const int arowoff = (lane & 7) + ((lane >> 3) & 1) * 8;
    const int nrowoff = (lane & 7) + ((lane >> 4) & 1) * 8;
    #pragma unroll
    for (int kk = 0; kk < 4; kk++) {
        uint32_t ah[2][4], bw[NT][4];
        const int akoff = kk * 32 + (lane >> 4) * 16;
        const int bkoff = kk * 32 + ((lane >> 3) & 1) * 16;
        #pragma unroll
        for (int m = 0; m < 2; m++) {
            uint32_t off = SWZ128((uint32_t)((mrow + m * 16 + arowoff) * 128 + akoff));
            ldsm4(ah[m], aT + off);
        }
        #pragma unroll
        for (int jb = 0; jb < NT; jb++) {
            uint32_t off = SWZ128((uint32_t)((nbase + jb * 16 + nrowoff) * 128 + bkoff));
            ldsm4(bw[jb], bT + off);
        }
        #pragma unroll
        for (int jb = 0; jb < NT; jb++)
            #pragma unroll
            for (int m = 0; m < 2; m++) {
                mma16816h(acc[m * 2 * NT + jb * 2],     ah[m], bw[jb][0], bw[jb][1]);
                mma16816h(acc[m * 2 * NT + jb * 2 + 1], ah[m], bw[jb][2], bw[jb][3]);
            }
    }
}

// ---------------------------------------------------------------------------
// Fused prep (device symbols bound in device code — R3 lesson).
// ---------------------------------------------------------------------------
__global__ void prep_all(const float* __restrict__ x,
                         const float* __restrict__ Wih,
                         const float* __restrict__ Whh) {
    const size_t NX = (size_t)Bv * Tv * Iv;
    const size_t NW = (size_t)Gv * Iv;
    size_t gid = (size_t)blockIdx.x * blockDim.x + threadIdx.x;
    size_t stride = (size_t)gridDim.x * blockDim.x;
    for (size_t i = gid; i < NX; i += stride) g_x_f16[i]   = __float2half(x[i]);
    for (size_t i = gid; i < NW; i += stride) g_Wih_f16[i] = __float2half(Wih[i]);
    for (size_t i = gid; i < NW; i += stride) g_Whh_f16[i] = __float2half(Whh[i]);
    for (size_t i = gid; i < (size_t)Bv * Hv; i += stride) g_h[0][i] = __float2half(0.0f);
    if (gid == 0) g_bar = 0u;
}

__global__ void dummy_kernel() {}

// ---------------------------------------------------------------------------
// Input GEMM (fp16 single-pass HMMA, proven R12)
// ---------------------------------------------------------------------------
#define G_STAGE 32768
#define G_SMEM  (2 * G_STAGE)

__device__ __forceinline__ void gemm_load(uint32_t sb, int s, int k0,
                                          int m0, int n0, int tid) {
    uint32_t base = sb + (uint32_t)s * G_STAGE;
    #pragma unroll
    for (int r = 0; r < 4; r++) {
        int idx = tid + r * 256;
        int row = idx >> 3, c = idx & 7;
        cp16(base + SWZ128((uint32_t)(row * 128 + c * 16)),
             g_x_f16 + (size_t)(m0 + row) * Iv + k0 + c * 8);
    }
    #pragma unroll
    for (int r = 0; r < 4; r++) {
        int idx = tid + r * 256;
        int row = idx >> 3, c = idx & 7;
        cp16(base + 16384 + SWZ128((uint32_t)(row * 128 + c * 16)),
             g_Wih_f16 + (size_t)(n0 + row) * Iv + k0 + c * 8);
    }
}

__global__ void __launch_bounds__(256, 1) gemm_in_mma(const float* __restrict__ bias)
{
    extern __shared__ char smem[];
    uint32_t sb = smem_u32(smem);
    const int tid = threadIdx.x, lane = tid & 31, wid = tid >> 5;
    const int m0 = blockIdx.y * 128, n0 = blockIdx.x * 128;

    float acc[16][4];
    #pragma unroll
    for (int i = 0; i < 16; i++)
        #pragma unroll
        for (int j = 0; j < 4; j++) acc[i][j] = 0.0f;

    gemm_load(sb, 0, 0, m0, n0, tid);
    CP_COMMIT();

    const int mrow = (wid & 3) * 32, nbase = (wid >> 2) * 64;
    for (int it = 0; it < 16; it++) {
        const int s = it & 1;
        if (it + 1 < 16) {
            gemm_load(sb, (it + 1) & 1, (it + 1) * 64, m0, n0, tid);
            CP_COMMIT();
            CP_WAIT(1);
        } else {
            CP_WAIT(0);
        }
        __syncthreads();
        uint32_t base = sb + (uint32_t)s * G_STAGE;
        warp_mma_f16<4>(base, base + 16384, mrow, nbase, lane, acc);
        __syncthreads();
    }

    #pragma unroll
    for (int m = 0; m < 2; m++)
        #pragma unroll
        for (int j = 0; j < 8; j++) {
            float* a = acc[m * 8 + j];
            int gr = m0 + (wid & 3) * 32 + m * 16 + (lane >> 2);
            int n  = n0 + (wid >> 2) * 64 + j * 8 + 2 * (lane & 3);
            float b0 = bias[n], b1 = bias[n + 1];
            int bi0 = gr >> 9, tt0 = gr & 511;
            __half2* o0 = (__half2*)(g_Gx + ((size_t)tt0 * Bv + bi0) * Gv + n);
            *o0 = __floats2half2_rn(a[0] + b0, a[1] + b1);
            int gr2 = gr + 8, bi2 = gr2 >> 9, tt2 = gr2 & 511;
            __half2* o2 = (__half2*)(g_Gx + ((size_t)tt2 * Bv + bi2) * Gv + n);
            *o2 = __floats2half2_rn(a[2] + b0, a[3] + b1);
        }
}

// ---------------------------------------------------------------------------
// Persistent LSTM recurrence. 128 CTAs x 256 threads, 1 CTA/SM.
// R13: TWO INDEPENDENT PARITY-GROUP PIPELINES. Group g (warps 4g..4g+3,
// tid g*128..g*128+127) loads ITS OWN parity chunks (k = g, g+2, g+4, g+6;
// K offsets *128) into its own 3 buffers and syncs with a named barrier —
// no full-CTA __syncthreads in the MMA loop. Full sync only at the epilogue
// join. Group0 additionally owns the Gx prefetch group.
// ---------------------------------------------------------------------------
#define WS     0                           /* 16 sub-chunks x 4KB = 64KB */
#define AB     65536                       /* 2 groups x 3 bufs x 16KB = 96KB */
#define GXS    (AB + 6 * 16384)            /* 163840: 2 x 5120 (fp16, 80B/row) */
#define CS     (GXS + 2 * 5120)            /* 174080: 512 fp32 = 2KB */
#define GS0    (CS + 2048)                 /* 176128: 64 x 33 fp32 = 8448 */
#define GS1    (GS0 + 8448)                /* 184576 */
#define P_SMEM (GS1 + 8448)                /* 193024 (~188.5KB) */

// Group (128 threads) loads one K-chunk of 128 (two 64-wide sub-tiles, 16KB).
__device__ __forceinline__ void group_loadA(uint32_t sb, int buf, int k0,
                                            const __half* __restrict__ hIn,
                                            int gtid) {
    uint32_t base = sb + AB + (uint32_t)buf * 16384;
    #pragma unroll
    for (int r = 0; r < 8; r++) {          // 1024 cp16 = 16KB
        int idx = gtid + r * 128;
        int sub = idx >> 9, rem = idx & 511;
        int row = rem >> 3, c = rem & 7;   // row = batch 0..63
        const __half* src = hIn + (size_t)row * Hv + k0 + sub * 64 + c * 8;
        cp16(base + sub * 8192 + SWZ128((uint32_t)(row * 128 + c * 16)), src);
    }
}

// Gx prefetch — GROUP0 ONLY (tid < 128), 2 cp16 per thread, own group.
__device__ __forceinline__ void load_gx_g0(uint32_t sb, int buf, int t, int j0,
                                           int tid) {
    const __half* gxbase = g_Gx + ((size_t)t * Bv) * Gv + j0;
    uint32_t dst = sb + GXS + (uint32_t)buf * 5120;
    #pragma unroll
    for (int r = 0; r < 2; r++) {          // 256 cp16 = 4KB (row stride 80B)
        int idx = tid + r * 128;           // tid in 0..127
        int b = idx >> 2, gate = idx & 3;
        cp16(dst + (uint32_t)(b * 80 + gate * 16),
             gxbase + (size_t)b * Gv + gate * Hv);
    }
    CP_COMMIT();
}

__global__ void __launch_bounds__(256, 1) lstm_persistent(float* __restrict__ dout)
{
    extern __shared__ char smem[];
    uint32_t sb = smem_u32(smem);
    const int tid = threadIdx.x, lane = tid & 31, wid = tid >> 5;
    const int j0 = blockIdx.x * 8;
    const int g = wid >> 2;                    // parity group (0: tid<128)
    const int gtid = tid & 127;
    const int mrow = (wid & 1) * 32;
    const int nbase = ((wid >> 1) & 1) * 16;
    const int bufbase = g * 3;
    const unsigned barid = (unsigned)(g + 1);

    // ---- Preload W_f16 tile: 32 gate rows x K=1024 = 64KB, sub-chunk-major
    #pragma unroll
    for (int r = 0; r < 16; r++) {             // 4096 cp16
        int idx = tid + r * 256;
        int chunk = idx >> 8, within = idx & 255;
        int row = within >> 3, c = within & 7;
        int gate = row >> 3, jc = row & 7;
        const __half* src = g_Whh_f16
            + (size_t)(gate * Hv + j0 + jc) * Hv + chunk * 64 + c * 8;
        cp16(sb + WS + chunk * 4096 + SWZ128((uint32_t)(row * 128 + c * 16)), src);
    }
    CP_COMMIT();
    CP_WAIT(0);
    __syncthreads();

    float* Gs0 = (float*)(smem + GS0);
    float* Gs1 = (float*)(smem + GS1);
    float* cs  = (float*)(smem + CS);
    cs[tid] = 0.0f;
    cs[tid + 256] = 0.0f;

    // prefetch Gx(0) — group0's pending ladder accounts for it
    if (g == 0) load_gx_g0(sb, 0, 0, j0, tid);
    __syncthreads();

    for (int t = 0; t < Tv; t++) {
        const __half* hIn = g_h[t & 1];
        __half* hOut      = g_h[(t + 1) & 1];

        float acc[4][4];
        #pragma unroll
        for (int i = 0; i < 4; i++)
            #pragma unroll
            for (int j = 0; j < 4; j++) acc[i][j] = 0.0f;

        // prologue: this group's first two parity chunks
        group_loadA(sb, bufbase + 0, (g)     * 128, hIn, gtid); CP_COMMIT();
        group_loadA(sb, bufbase + 1, (g + 2) * 128, hIn, gtid); CP_COMMIT();

        // group-private pipeline over its 4 parity chunks.
        // group0 pending at i=0: {Gx, A0, A1} -> WAIT(1) completes Gx+A0.
        // group1 pending at i=0: {A0, A1}     -> WAIT(1) completes A0.
        #pragma unroll
        for (int i = 0; i < 4; i++) {
            if (i < 3) { CP_WAIT(1); } else { CP_WAIT(0); }
            asm volatile("bar.sync %0, 128;" :: "r"(barid) : "memory");
            const int kc = g + 2 * i;          // global chunk index
            uint32_t aT = sb + AB + (uint32_t)(bufbase + (i % 3)) * 16384;
            warp_mma_f16<1>(aT,        sb + WS + (uint32_t)(2 * kc) * 4096,
                            mrow, nbase, lane, acc);
            warp_mma_f16<1>(aT + 8192, sb + WS + (uint32_t)(2 * kc + 1) * 4096,
                            mrow, nbase, lane, acc);
            if (i + 2 < 4) {
                group_loadA(sb, bufbase + ((i + 2) % 3), (g + 2 * (i + 2)) * 128,
                            hIn, gtid);
                CP_COMMIT();
            }
        }

        // Stage partial gates (per parity buffer), then CTA-wide join
        float* Gs = g ? Gs1 : Gs0;
        #pragma unroll
        for (int m = 0; m < 2; m++)
            #pragma unroll
            for (int p = 0; p < 2; p++) {
                float* a = acc[m * 2 + p];
                int r0 = mrow + m * 16 + (lane >> 2);
                int cc = nbase + p * 8 + 2 * (lane & 3);
                Gs[r0 * 33 + cc]           = a[0];
                Gs[r0 * 33 + cc + 1]       = a[1];
                Gs[(r0 + 8) * 33 + cc]     = a[2];
                Gs[(r0 + 8) * 33 + cc + 1] = a[3];
            }
        __syncthreads();

        // Fused cell update (Gx fp16 from SMEM); dout deferred past arrival
        const __half* gx = (const __half*)(smem + GXS + (uint32_t)(t & 1) * 5120);
        float hn_s[2], cn_s[2];
        #pragma unroll
        for (int p = 0; p < 2; p++) {
            int cell = tid + p * 256;
            int b = cell >> 3, jc = cell & 7;
            const __half* gxr = gx + b * 40;
            float gi = Gs0[b * 33 + jc]      + Gs1[b * 33 + jc]      + __half2float(gxr[jc]);
            float gf = Gs0[b * 33 + 8 + jc]  + Gs1[b * 33 + 8 + jc]  + __half2float(gxr[8 + jc]);
            float gg = Gs0[b * 33 + 16 + jc] + Gs1[b * 33 + 16 + jc] + __half2float(gxr[16 + jc]);
            float go = Gs0[b * 33 + 24 + jc] + Gs1[b * 33 + 24 + jc] + __half2float(gxr[24 + jc]);

            float c_old = cs[cell];
            float cn = sigm(gf) * c_old + sigm(gi) * tanh_fast(gg);
            float hn = sigm(go) * tanh_fast(cn);
            cs[cell] = cn;
            hn_s[p] = hn; cn_s[p] = cn;

            hOut[b * Hv + j0 + jc] = __float2half(hn);
        }
        __syncthreads();

        // prefetch next step's Gx during the barrier window (group0 only)
        if (g == 0 && t + 1 < Tv) load_gx_g0(sb, (t + 1) & 1, t + 1, j0, tid);

        // arrive: h(t+1) published
        if (tid == 0) {
            unsigned int ignored;
            asm volatile("atom.add.release.gpu.u32 %0, [%1], 1;"
                         : "=r"(ignored) : "l"(&g_bar) : "memory");
        }

        // off-critical-path: stream outputs to DRAM
        #pragma unroll
        for (int p = 0; p < 2; p++) {
            int cell = tid + p * 256;
            int b = cell >> 3, jc = cell & 7;
            dout[(size_t)b * Tv * Hv + (size_t)t * Hv + j0 + jc] = hn_s[p];
            if (t == Tv - 1) {
                size_t obase = (size_t)Bv * Tv * Hv;
                int hidx = b * Hv + j0 + jc;
                dout[obase + hidx] = hn_s[p];                    // h_T
                dout[obase + (size_t)Bv * Hv + hidx] = cn_s[p];  // c_T
            }
        }

        // spin for all arrivals of step t
        if (tid == 0) {
            unsigned int target = 128u * (unsigned int)(t + 1);
            unsigned int cur;
            do {
                asm volatile("ld.acquire.gpu.u32 %0, [%1];"
                             : "=r"(cur) : "l"(&g_bar) : "memory");
                if (cur >= target) break;
                asm volatile("nanosleep.u32 16;");
            } while (true);
        }
        __syncthreads();
    }
}

// ---------------------------------------------------------------------------
// Launch: prep_all(1), gemm(2), dummy(3), persistent(4) — keeps ncu -s 5
// capturing lstm_persistent.
// ---------------------------------------------------------------------------
extern "C" void kernel_launch(void* const* d_in, const int* in_sizes, int n_in,
                              void* d_out, int out_size)
{
    const float* x    = (const float*)d_in[0];  // [B, T, I]
    const float* Wih  = (const float*)d_in[1];  // [4H, I]
    const float* Whh  = (const float*)d_in[2];  // [4H, H]
    const float* bias = (const float*)d_in[3];  // [4H]
    float* out = (float*)d_out;
    (void)in_sizes; (void)n_in; (void)out_size;

    cudaFuncSetAttribute(gemm_in_mma,     cudaFuncAttributeMaxDynamicSharedMemorySize, G_SMEM);
    cudaFuncSetAttribute(lstm_persistent, cudaFuncAttributeMaxDynamicSharedMemorySize, P_SMEM);

    prep_all<<<4096, 256>>>(x, Wih, Whh);

    dim3 ggrid(Gv / 128, (Bv * Tv) / 128);   // (32, 256)
    gemm_in_mma<<<ggrid, 256, G_SMEM>>>(bias);

    dummy_kernel<<<1, 32>>>();

    lstm_persistent<<<128, 256, P_SMEM>>>(out);
}

// round 14
// speedup vs baseline: 2.2398x; 1.0688x over previous
#include <cuda_runtime.h>
#include <cuda_bf16.h>
#include <cuda_fp16.h>
#include <cstdint>
#include <math.h>

#define Bv 64
#define Tv 512
#define Iv 1024
#define Hv 1024
#define Gv 4096   // 4*H

// ---------------------------------------------------------------------------
// Static device scratch (all fp16)
// ---------------------------------------------------------------------------
__device__ __half g_Gx[(size_t)Tv * Bv * Gv];             // 256MB [T][B][4H]
__device__ __half g_x_f16[(size_t)Bv * Tv * Iv];          // 64MB
__device__ __half g_Wih_f16[(size_t)Gv * Iv];             // 8MB
__device__ __half g_Whh_f16[(size_t)Gv * Hv];             // 8MB
__device__ __half g_h[2][Bv * Hv];                        // fp16 h
__device__ unsigned int g_bar2[2];                        // per-batch-group

// ---------------------------------------------------------------------------
// Helpers
// ---------------------------------------------------------------------------
__device__ __forceinline__ uint32_t smem_u32(const void* p) {
    uint32_t a;
    asm("{ .reg .u64 t; cvta.to.shared.u64 t, %1; cvt.u32.u64 %0, t; }"
        : "=r"(a) : "l"(p));
    return a;
}

#define SWZ128(o) ((o) ^ (((o) >> 3) & 0x70))

__device__ __forceinline__ void cp16(uint32_t dst, const void* src) {
    asm volatile("cp.async.cg.shared.global [%0], [%1], 16;" :: "r"(dst), "l"(src));
}
#define CP_COMMIT() asm volatile("cp.async.commit_group;" ::: "memory")
#define CP_WAIT(n)  asm volatile("cp.async.wait_group %0;" :: "n"(n) : "memory")

__device__ __forceinline__ void ldsm4(uint32_t* r, uint32_t addr) {
    asm volatile("ldmatrix.sync.aligned.m8n8.x4.shared.b16 {%0,%1,%2,%3}, [%4];"
        : "=r"(r[0]), "=r"(r[1]), "=r"(r[2]), "=r"(r[3]) : "r"(addr));
}

__device__ __forceinline__ void mma16816h(float* d, const uint32_t* a,
                                          uint32_t b0, uint32_t b1) {
    asm volatile(
        "mma.sync.aligned.m16n8k16.row.col.f32.f16.f16.f32 "
        "{%0,%1,%2,%3}, {%4,%5,%6,%7}, {%8,%9}, {%0,%1,%2,%3};"
        : "+f"(d[0]), "+f"(d[1]), "+f"(d[2]), "+f"(d[3])
        : "r"(a[0]), "r"(a[1]), "r"(a[2]), "r"(a[3]), "r"(b0), "r"(b1));
}

__device__ __forceinline__ float sigm(float x) {
    return 1.0f / (1.0f + __expf(-x));
}
__device__ __forceinline__ float tanh_fast(float x) {
    float cx = fminf(fmaxf(x, -10.0f), 10.0f);
    float e = __expf(2.0f * cx);
    return (e - 1.0f) / (e + 1.0f);
}

// ---------------------------------------------------------------------------
// fp16 single-pass warp MMA over one 64-wide K sub-tile.
// MT m-tiles of 16 rows, NT n-tiles of 16 cols.
// acc layout: acc[m*2*NT + jb*2 + p][4]
// ---------------------------------------------------------------------------
template <int MT, int NT>
__device__ __forceinline__ void warp_mma_f16(
    uint32_t aT, uint32_t bT, int mrow, int nbase, int lane, float acc[][4])
{
    const int arowoff = (lane & 7) + ((lane >> 3) & 1) * 8;
    const int nrowoff = (lane & 7) + ((lane >> 4) & 1) * 8;
    #pragma unroll
    for (int kk = 0; kk < 4; kk++) {
        uint32_t ah[MT][4], bw[NT][4];
        const int akoff = kk * 32 + (lane >> 4) * 16;
        const int bkoff = kk * 32 + ((lane >> 3) & 1) * 16;
        #pragma unroll
        for (int m = 0; m < MT; m++) {
            uint32_t off = SWZ128((uint32_t)((mrow + m * 16 + arowoff) * 128 + akoff));
            ldsm4(ah[m], aT + off);
        }
        #pragma unroll
        for (int jb = 0; jb < NT; jb++) {
            uint32_t off = SWZ128((uint32_t)((nbase + jb * 16 + nrowoff) * 128 + bkoff));
            ldsm4(bw[jb], bT + off);
        }
        #pragma unroll
        for (int jb = 0; jb < NT; jb++)
            #pragma unroll
            for (int m = 0; m < MT; m++) {
                mma16816h(acc[m * 2 * NT + jb * 2],     ah[m], bw[jb][0], bw[jb][1]);
                mma16816h(acc[m * 2 * NT + jb * 2 + 1], ah[m], bw[jb][2], bw[jb][3]);
            }
    }
}

// ---------------------------------------------------------------------------
// Fused prep (device symbols bound in device code — R3 lesson).
// ---------------------------------------------------------------------------
__global__ void prep_all(const float* __restrict__ x,
                         const float* __restrict__ Wih,
                         const float* __restrict__ Whh) {
    const size_t NX = (size_t)Bv * Tv * Iv;
    const size_t NW = (size_t)Gv * Iv;
    size_t gid = (size_t)blockIdx.x * blockDim.x + threadIdx.x;
    size_t stride = (size_t)gridDim.x * blockDim.x;
    for (size_t i = gid; i < NX; i += stride) g_x_f16[i]   = __float2half(x[i]);
    for (size_t i = gid; i < NW; i += stride) g_Wih_f16[i] = __float2half(Wih[i]);
    for (size_t i = gid; i < NW; i += stride) g_Whh_f16[i] = __float2half(Whh[i]);
    for (size_t i = gid; i < (size_t)Bv * Hv; i += stride) g_h[0][i] = __float2half(0.0f);
    if (gid < 2) g_bar2[gid] = 0u;
}

__global__ void dummy_kernel() {}

// ---------------------------------------------------------------------------
// Input GEMM (fp16 single-pass HMMA, proven R12/R13)
// ---------------------------------------------------------------------------
#define G_STAGE 32768
#define G_SMEM  (2 * G_STAGE)

__device__ __forceinline__ void gemm_load(uint32_t sb, int s, int k0,
                                          int m0, int n0, int tid) {
    uint32_t base = sb + (uint32_t)s * G_STAGE;
    #pragma unroll
    for (int r = 0; r < 4; r++) {
        int idx = tid + r * 256;
        int row = idx >> 3, c = idx & 7;
        cp16(base + SWZ128((uint32_t)(row * 128 + c * 16)),
             g_x_f16 + (size_t)(m0 + row) * Iv + k0 + c * 8);
    }
    #pragma unroll
    for (int r = 0; r < 4; r++) {
        int idx = tid + r * 256;
        int row = idx >> 3, c = idx & 7;
        cp16(base + 16384 + SWZ128((uint32_t)(row * 128 + c * 16)),
             g_Wih_f16 + (size_t)(n0 + row) * Iv + k0 + c * 8);
    }
}

__global__ void __launch_bounds__(256, 1) gemm_in_mma(const float* __restrict__ bias)
{
    extern __shared__ char smem[];
    uint32_t sb = smem_u32(smem);
    const int tid = threadIdx.x, lane = tid & 31, wid = tid >> 5;
    const int m0 = blockIdx.y * 128, n0 = blockIdx.x * 128;

    float acc[16][4];
    #pragma unroll
    for (int i = 0; i < 16; i++)
        #pragma unroll
        for (int j = 0; j < 4; j++) acc[i][j] = 0.0f;

    gemm_load(sb, 0, 0, m0, n0, tid);
    CP_COMMIT();

    const int mrow = (wid & 3) * 32, nbase = (wid >> 2) * 64;
    for (int it = 0; it < 16; it++) {
        const int s = it & 1;
        if (it + 1 < 16) {
            gemm_load(sb, (it + 1) & 1, (it + 1) * 64, m0, n0, tid);
            CP_COMMIT();
            CP_WAIT(1);
        } else {
            CP_WAIT(0);
        }
        __syncthreads();
        uint32_t base = sb + (uint32_t)s * G_STAGE;
        warp_mma_f16<2, 4>(base, base + 16384, mrow, nbase, lane, acc);
        __syncthreads();
    }

    #pragma unroll
    for (int m = 0; m < 2; m++)
        #pragma unroll
        for (int j = 0; j < 8; j++) {
            float* a = acc[m * 8 + j];
            int gr = m0 + (wid & 3) * 32 + m * 16 + (lane >> 2);
            int n  = n0 + (wid >> 2) * 64 + j * 8 + 2 * (lane & 3);
            float b0 = bias[n], b1 = bias[n + 1];
            int bi0 = gr >> 9, tt0 = gr & 511;
            __half2* o0 = (__half2*)(g_Gx + ((size_t)tt0 * Bv + bi0) * Gv + n);
            *o0 = __floats2half2_rn(a[0] + b0, a[1] + b1);
            int gr2 = gr + 8, bi2 = gr2 >> 9, tt2 = gr2 & 511;
            __half2* o2 = (__half2*)(g_Gx + ((size_t)tt2 * Bv + bi2) * Gv + n);
            *o2 = __floats2half2_rn(a[2] + b0, a[3] + b1);
        }
}

// ---------------------------------------------------------------------------
// Persistent LSTM recurrence, R14 batch-split:
// 128 CTAs = 2 batch-groups x 64 CTAs. CTA = 32 batch rows x 16 hidden cols
// (64 gate rows). W_f16 tile 128KB SMEM-resident. Two independent per-group
// barriers (a group consumes only h rows it produces). Parity-group pipelines
// with named barriers (R13). Gx prefetched during the barrier spin.
// ---------------------------------------------------------------------------
#define WS     0                           /* 16 sub-chunks x 8KB = 128KB */
#define AB     131072                      /* 2 groups x 3 bufs x 8KB = 48KB */
#define GXS    (AB + 6 * 8192)             /* 180224: 2 x 4608 (fp16 144B/row) */
#define CS     (GXS + 2 * 4608)            /* 189440: 512 fp32 = 2KB */
#define GS0    (CS + 2048)                 /* 191488: 32 x 66 fp32 = 8448 */
#define GS1    (GS0 + 8448)                /* 199936 */
#define P_SMEM (GS1 + 8448)                /* 208384 (~203.5KB) */

// Group (128 threads) loads one K-chunk of 128 for 32 batch rows (8KB).
__device__ __forceinline__ void group_loadA(uint32_t sb, int buf, int k0,
                                            const __half* __restrict__ hIn,
                                            int b0, int gtid) {
    uint32_t base = sb + AB + (uint32_t)buf * 8192;
    #pragma unroll
    for (int r = 0; r < 4; r++) {          // 512 cp16 = 8KB
        int idx = gtid + r * 128;
        int sub = idx >> 8, rem = idx & 255;
        int row = rem >> 3, c = rem & 7;   // row = 0..31
        const __half* src = hIn + (size_t)(b0 + row) * Hv + k0 + sub * 64 + c * 8;
        cp16(base + sub * 4096 + SWZ128((uint32_t)(row * 128 + c * 16)), src);
    }
}

// Gx prefetch — GROUP0 ONLY (tid < 128), 2 cp16 per thread, own group.
// Slice: 32 batch rows x 64 gate cols fp16, row stride 144B.
__device__ __forceinline__ void load_gx_g0(uint32_t sb, int buf, int t,
                                           int b0, int j0, int tid) {
    const __half* gxbase = g_Gx + ((size_t)t * Bv + b0) * Gv + j0;
    uint32_t dst = sb + GXS + (uint32_t)buf * 4608;
    #pragma unroll
    for (int r = 0; r < 2; r++) {          // 256 cp16 = 4KB
        int idx = tid + r * 128;           // 0..255
        int b = idx >> 3, rem = idx & 7;
        int gate = rem >> 1, hf = rem & 1;
        cp16(dst + (uint32_t)(b * 144 + gate * 32 + hf * 16),
             gxbase + (size_t)b * Gv + gate * Hv + hf * 8);
    }
    CP_COMMIT();
}

__global__ void __launch_bounds__(256, 1) lstm_persistent(float* __restrict__ dout)
{
    extern __shared__ char smem[];
    uint32_t sb = smem_u32(smem);
    const int tid = threadIdx.x, lane = tid & 31, wid = tid >> 5;
    const int bg = blockIdx.x >> 6;            // batch group 0/1
    const int b0 = bg * 32;                    // first batch row
    const int j0 = (blockIdx.x & 63) * 16;     // first hidden col
    const int g = wid >> 2;                    // parity group (0: tid<128)
    const int gtid = tid & 127;
    const int mrow = (wid & 1) * 16;           // m16 tile
    const int nbase = ((wid >> 1) & 1) * 32;   // n32 (2 n-tiles of 16)
    const int bufbase = g * 3;
    const unsigned barid = (unsigned)(g + 1);
    unsigned int* barp = &g_bar2[bg];

    // ---- Preload W_f16 tile: 64 gate rows x K=1024 = 128KB, sub-chunk-major
    #pragma unroll
    for (int r = 0; r < 32; r++) {             // 8192 cp16
        int idx = tid + r * 256;
        int chunk = idx >> 9, within = idx & 511;
        int row = within >> 3, c = within & 7;   // row = gate*16 + jc (0..63)
        int gate = row >> 4, jc = row & 15;
        const __half* src = g_Whh_f16
            + (size_t)(gate * Hv + j0 + jc) * Hv + chunk * 64 + c * 8;
        cp16(sb + WS + chunk * 8192 + SWZ128((uint32_t)(row * 128 + c * 16)), src);
    }
    CP_COMMIT();
    CP_WAIT(0);
    __syncthreads();

    float* Gs0 = (float*)(smem + GS0);
    float* Gs1 = (float*)(smem + GS1);
    float* cs  = (float*)(smem + CS);
    cs[tid] = 0.0f;
    cs[tid + 256] = 0.0f;

    // prefetch Gx(0) — group0's pending ladder accounts for it
    if (g == 0) load_gx_g0(sb, 0, 0, b0, j0, tid);
    __syncthreads();

    for (int t = 0; t < Tv; t++) {
        const __half* hIn = g_h[t & 1];
        __half* hOut      = g_h[(t + 1) & 1];

        float acc[4][4];
        #pragma unroll
        for (int i = 0; i < 4; i++)
            #pragma unroll
            for (int j = 0; j < 4; j++) acc[i][j] = 0.0f;

        // prologue: this group's first two parity chunks
        group_loadA(sb, bufbase + 0, (g)     * 128, hIn, b0, gtid); CP_COMMIT();
        group_loadA(sb, bufbase + 1, (g + 2) * 128, hIn, b0, gtid); CP_COMMIT();

        // group-private pipeline (group0 pending at i=0: {Gx,A0,A1} -> WAIT(1))
        #pragma unroll
        for (int i = 0; i < 4; i++) {
            if (i < 3) { CP_WAIT(1); } else { CP_WAIT(0); }
            asm volatile("bar.sync %0, 128;" :: "r"(barid) : "memory");
            const int kc = g + 2 * i;          // global chunk index
            uint32_t aT = sb + AB + (uint32_t)(bufbase + (i % 3)) * 8192;
            warp_mma_f16<1, 2>(aT,        sb + WS + (uint32_t)(2 * kc) * 8192,
                               mrow, nbase, lane, acc);
            warp_mma_f16<1, 2>(aT + 4096, sb + WS + (uint32_t)(2 * kc + 1) * 8192,
                               mrow, nbase, lane, acc);
            if (i + 2 < 4) {
                group_loadA(sb, bufbase + ((i + 2) % 3), (g + 2 * (i + 2)) * 128,
                            hIn, b0, gtid);
                CP_COMMIT();
            }
        }

        // Stage partial gates (per parity buffer), then CTA-wide join
        float* Gs = g ? Gs1 : Gs0;
        #pragma unroll
        for (int jb = 0; jb < 2; jb++)
            #pragma unroll
            for (int p = 0; p < 2; p++) {
                float* a = acc[jb * 2 + p];
                int r0 = mrow + (lane >> 2);
                int cc = nbase + jb * 16 + p * 8 + 2 * (lane & 3);
                Gs[r0 * 66 + cc]           = a[0];
                Gs[r0 * 66 + cc + 1]       = a[1];
                Gs[(r0 + 8) * 66 + cc]     = a[2];
                Gs[(r0 + 8) * 66 + cc + 1] = a[3];
            }
        __syncthreads();

        // Fused cell update: 512 cells (32 batch x 16 hidden cols)
        const __half* gx = (const __half*)(smem + GXS + (uint32_t)(t & 1) * 4608);
        float hn_s[2], cn_s[2];
        #pragma unroll
        for (int p = 0; p < 2; p++) {
            int cell = tid + p * 256;
            int b = cell >> 4, jc = cell & 15;
            const __half* gxr = gx + b * 72;
            float gi = Gs0[b * 66 + jc]      + Gs1[b * 66 + jc]      + __half2float(gxr[jc]);
            float gf = Gs0[b * 66 + 16 + jc] + Gs1[b * 66 + 16 + jc] + __half2float(gxr[16 + jc]);
            float gg = Gs0[b * 66 + 32 + jc] + Gs1[b * 66 + 32 + jc] + __half2float(gxr[32 + jc]);
            float go = Gs0[b * 66 + 48 + jc] + Gs1[b * 66 + 48 + jc] + __half2float(gxr[48 + jc]);

            float c_old = cs[cell];
            float cn = sigm(gf) * c_old + sigm(gi) * tanh_fast(gg);
            float hn = sigm(go) * tanh_fast(cn);
            cs[cell] = cn;
            hn_s[p] = hn; cn_s[p] = cn;

            hOut[(size_t)(b0 + b) * Hv + j0 + jc] = __float2half(hn);
        }
        __syncthreads();

        // prefetch next step's Gx during the barrier window (group0 only)
        if (g == 0 && t + 1 < Tv) load_gx_g0(sb, (t + 1) & 1, t + 1, b0, j0, tid);

        // arrive: this CTA's h(t+1) rows published (group-local barrier)
        if (tid == 0) {
            unsigned int ignored;
            asm volatile("atom.add.release.gpu.u32 %0, [%1], 1;"
                         : "=r"(ignored) : "l"(barp) : "memory");
        }

        // off-critical-path: stream outputs to DRAM
        #pragma unroll
        for (int p = 0; p < 2; p++) {
            int cell = tid + p * 256;
            int b = cell >> 4, jc = cell & 15;
            int batch = b0 + b;
            dout[(size_t)batch * Tv * Hv + (size_t)t * Hv + j0 + jc] = hn_s[p];
            if (t == Tv - 1) {
                size_t obase = (size_t)Bv * Tv * Hv;
                int hidx = batch * Hv + j0 + jc;
                dout[obase + hidx] = hn_s[p];                    // h_T
                dout[obase + (size_t)Bv * Hv + hidx] = cn_s[p];  // c_T
            }
        }

        // spin for this batch-group's 64 arrivals of step t
        if (tid == 0) {
            unsigned int target = 64u * (unsigned int)(t + 1);
            unsigned int cur;
            do {
                asm volatile("ld.acquire.gpu.u32 %0, [%1];"
                             : "=r"(cur) : "l"(barp) : "memory");
                if (cur >= target) break;
                asm volatile("nanosleep.u32 16;");
            } while (true);
        }
        __syncthreads();
    }
}

// ---------------------------------------------------------------------------
// Launch: prep_all(1), gemm(2), dummy(3), persistent(4) — keeps ncu -s 5
// capturing lstm_persistent.
// ---------------------------------------------------------------------------
extern "C" void kernel_launch(void* const* d_in, const int* in_sizes, int n_in,
                              void* d_out, int out_size)
{
    const float* x    = (const float*)d_in[0];  // [B, T, I]
    const float* Wih  = (const float*)d_in[1];  // [4H, I]
    const float* Whh  = (const float*)d_in[2];  // [4H, H]
    const float* bias = (const float*)d_in[3];  // [4H]
    float* out = (float*)d_out;
    (void)in_sizes; (void)n_in; (void)out_size;

    cudaFuncSetAttribute(gemm_in_mma,     cudaFuncAttributeMaxDynamicSharedMemorySize, G_SMEM);
    cudaFuncSetAttribute(lstm_persistent, cudaFuncAttributeMaxDynamicSharedMemorySize, P_SMEM);

    prep_all<<<4096, 256>>>(x, Wih, Whh);

    dim3 ggrid(Gv / 128, (Bv * Tv) / 128);   // (32, 256)
    gemm_in_mma<<<ggrid, 256, G_SMEM>>>(bias);

    dummy_kernel<<<1, 32>>>();

    lstm_persistent<<<128, 256, P_SMEM>>>(out);
}